// round 11
// baseline (speedup 1.0000x reference)
#include <cuda_runtime.h>
#include <cuda_bf16.h>
#include <math.h>
#include <stdint.h>

// Problem dims (fixed)
#define BB 4
#define SS 2048
#define EE 512
#define HH 8
#define DD 64
#define FF 2048
#define MM (BB*SS)          // 8192 tokens
#define LN_EPS 1e-5f
#define K2E 1024            // A-split data length (hi|lo) for K=512
#define K2F 4096            // A-split data length (hi|lo) for K=2048
#define K3E 1536            // B-split (hi|hi|lo) / logical K for K=512
#define K3F 6144            // logical K for K=2048
#define SAE 1088            // actA row stride (K2E + 64 pad) -> 2176B, non-pow2
#define SAF 4160            // actB row stride (K2F + 64 pad) -> 8320B, non-pow2

// ---------------- scratch (device globals; no allocation) ----------------
__device__ __nv_bfloat16 g_Qb[(size_t)MM*EE];
__device__ __nv_bfloat16 g_Kb[(size_t)MM*EE];
__device__ __nv_bfloat16 g_Vb[(size_t)MM*EE];
__device__ float g_tmp[MM*EE];
__device__ float g_x1 [MM*EE];
__device__ __nv_bfloat16 g_actA[(size_t)MM*SAE];   // split activations (hi|lo), padded stride
__device__ __nv_bfloat16 g_actB[(size_t)MM*SAF];   // split FFN1 output (hi|lo), padded stride
__device__ __nv_bfloat16 g_ws  [(size_t)FF*K3E];   // split weights (hi|hi|lo)

// ================= helpers =================
__device__ __forceinline__ uint32_t smem_u32(const void* p) {
    uint32_t a;
    asm("{ .reg .u64 t; cvta.to.shared.u64 t, %1; cvt.u32.u64 %0, t; }"
        : "=r"(a) : "l"(p));
    return a;
}
__device__ __forceinline__ void cpasync16(uint32_t s, const void* g) {
    asm volatile("cp.async.cg.shared.global [%0], [%1], 16;" :: "r"(s), "l"(g));
}
__device__ __forceinline__ void cp_commit() {
    asm volatile("cp.async.commit_group;" ::: "memory");
}
__device__ __forceinline__ void ldm_x4(uint32_t* r, uint32_t addr) {
    asm volatile("ldmatrix.sync.aligned.m8n8.x4.shared.b16 {%0,%1,%2,%3}, [%4];"
        : "=r"(r[0]), "=r"(r[1]), "=r"(r[2]), "=r"(r[3]) : "r"(addr));
}
__device__ __forceinline__ void ldm_x4_t(uint32_t* r, uint32_t addr) {
    asm volatile("ldmatrix.sync.aligned.m8n8.x4.trans.shared.b16 {%0,%1,%2,%3}, [%4];"
        : "=r"(r[0]), "=r"(r[1]), "=r"(r[2]), "=r"(r[3]) : "r"(addr));
}
__device__ __forceinline__ void mma_bf16(float* c, const uint32_t* a,
                                         uint32_t b0, uint32_t b1) {
    asm volatile(
        "mma.sync.aligned.m16n8k16.row.col.f32.bf16.bf16.f32 "
        "{%0,%1,%2,%3}, {%4,%5,%6,%7}, {%8,%9}, {%0,%1,%2,%3};"
        : "+f"(c[0]), "+f"(c[1]), "+f"(c[2]), "+f"(c[3])
        : "r"(a[0]), "r"(a[1]), "r"(a[2]), "r"(a[3]), "r"(b0), "r"(b1));
}
__device__ __forceinline__ uint32_t pk2(__nv_bfloat16 a, __nv_bfloat16 b) {
    __nv_bfloat162 t = __halves2bfloat162(a, b);
    return *reinterpret_cast<uint32_t*>(&t);
}
__device__ __forceinline__ uint32_t pk2f(float a, float b) {
    return pk2(__float2bfloat16(a), __float2bfloat16(b));
}

// ================= HMMA (mma.sync) GEMM =================
// Logical: C[M,N] = sum_{K3} A'[M,*] @ B'[N,K3]^T,
// A stored [M, strideA] rows holding (hi|lo) in first Ka elems; k-loop remaps
// A as hi,lo,hi against B stored [N, 3K] as (hi|hi|lo): Ah*Bh + Al*Bh + Ah*Bl.
// EPI: 1 = +bias+res fp32 ; 2 = gelu(+bias) -> split(hi|lo) bf16, row stride strideCs ;
//      3 = +bias -> plain bf16
// Tile 128x128, BK=32, 8 warps (4m x 2n), 2-stage double buffer (R7 engine).
#define SROW 40

template<int EPI>
__global__ __launch_bounds__(256) void mma_gemm(
    const __nv_bfloat16* __restrict__ A, const __nv_bfloat16* __restrict__ Bw,
    const float* __restrict__ bias, const float* __restrict__ res,
    float* __restrict__ C, __nv_bfloat16* __restrict__ Cs,
    int N, int Ka, int K3, int strideA, int strideCs)
{
    __shared__ __nv_bfloat16 As[2][128 * SROW];
    __shared__ __nv_bfloat16 Bs[2][128 * SROW];

    const int tid = threadIdx.x;
    const int wid = tid >> 5, lid = tid & 31;
    const int warp_m = wid & 3;
    const int warp_n = wid >> 2;
    const int m0 = blockIdx.y * 128;
    const int n0 = blockIdx.x * 128;

    const uint32_t sA0 = smem_u32(As[0]), sA1 = smem_u32(As[1]);
    const uint32_t sB0 = smem_u32(Bs[0]), sB1 = smem_u32(Bs[1]);

    float acc[2][8][4];
    #pragma unroll
    for (int mt = 0; mt < 2; mt++)
        #pragma unroll
        for (int nt = 0; nt < 8; nt++)
            #pragma unroll
            for (int q = 0; q < 4; q++) acc[mt][nt][q] = 0.f;

    const int nK = K3 / 32;
    const int ka32 = Ka / 32;     // A index wraps back to hi past this

    const int r0c = tid >> 2, c0c = (tid & 3);
    const int r1c = (tid + 256) >> 2, c1c = ((tid + 256) & 3);
    const uint32_t so0 = (uint32_t)(r0c * SROW + c0c * 8) * 2;
    const uint32_t so1 = (uint32_t)(r1c * SROW + c1c * 8) * 2;

    #define ISSUE(kt, b) do {                                                    \
        int ktA_ = (kt) < ka32 ? (kt) : (kt) - ka32;                             \
        const __nv_bfloat16* Ag = A + (size_t)m0 * strideA + (size_t)ktA_ * 32;  \
        const __nv_bfloat16* Bg = Bw + (size_t)n0 * K3 + (size_t)(kt) * 32;      \
        uint32_t _a = (b) ? sA1 : sA0, _b = (b) ? sB1 : sB0;                     \
        cpasync16(_a + so0, Ag + (size_t)r0c * strideA + c0c * 8);               \
        cpasync16(_a + so1, Ag + (size_t)r1c * strideA + c1c * 8);               \
        cpasync16(_b + so0, Bg + (size_t)r0c * K3 + c0c * 8);                    \
        cpasync16(_b + so1, Bg + (size_t)r1c * K3 + c1c * 8);                    \
        cp_commit();                                                             \
    } while (0)

    ISSUE(0, 0);

    for (int kt = 0; kt < nK; kt++) {
        const int b = kt & 1;
        if (kt + 1 < nK) {
            ISSUE(kt + 1, b ^ 1);
            asm volatile("cp.async.wait_group 1;" ::: "memory");
        } else {
            asm volatile("cp.async.wait_group 0;" ::: "memory");
        }
        __syncthreads();

        const uint32_t sAb = b ? sA1 : sA0;
        const uint32_t sBb = b ? sB1 : sB0;

        #pragma unroll
        for (int ks = 0; ks < 2; ks++) {
            const int kof = ks * 16;
            uint32_t afr[2][4];
            #pragma unroll
            for (int mt = 0; mt < 2; mt++) {
                uint32_t addr = sAb +
                    (uint32_t)((warp_m * 32 + mt * 16 + (lid & 15)) * SROW
                               + kof + (lid >> 4) * 8) * 2;
                ldm_x4(afr[mt], addr);
            }
            uint32_t bfr[4][4];
            #pragma unroll
            for (int q = 0; q < 4; q++) {
                const int grp = lid >> 3;
                const int n = warp_n * 64 + q * 16 + (grp >> 1) * 8 + (lid & 7);
                uint32_t addr = sBb +
                    (uint32_t)(n * SROW + kof + (grp & 1) * 8) * 2;
                ldm_x4(bfr[q], addr);
            }
            #pragma unroll
            for (int mt = 0; mt < 2; mt++)
                #pragma unroll
                for (int nt = 0; nt < 8; nt++)
                    mma_bf16(acc[mt][nt], afr[mt],
                             bfr[nt >> 1][(nt & 1) * 2],
                             bfr[nt >> 1][(nt & 1) * 2 + 1]);
        }
        __syncthreads();
    }
    #undef ISSUE

    // ---- epilogue (direct from fragments) ----
    const int g = lid >> 2, tig = lid & 3;
    const int row_base = m0 + warp_m * 32;
    const int col_base = n0 + warp_n * 64;
    #pragma unroll
    for (int mt = 0; mt < 2; mt++) {
        #pragma unroll
        for (int half = 0; half < 2; half++) {
            const int r = row_base + mt * 16 + g + half * 8;
            #pragma unroll
            for (int nt = 0; nt < 8; nt++) {
                const int cidx = col_base + nt * 8 + tig * 2;
                float v0 = acc[mt][nt][half * 2 + 0] + bias[cidx];
                float v1 = acc[mt][nt][half * 2 + 1] + bias[cidx + 1];
                if (EPI == 1) {
                    const float2 rv = *(const float2*)(res + (size_t)r * N + cidx);
                    v0 += rv.x; v1 += rv.y;
                }
                if (EPI == 2) {
                    v0 = 0.5f * v0 * (1.0f + erff(v0 * 0.70710678118654752f));
                    v1 = 0.5f * v1 * (1.0f + erff(v1 * 0.70710678118654752f));
                    __nv_bfloat16 h0 = __float2bfloat16(v0);
                    __nv_bfloat16 h1 = __float2bfloat16(v1);
                    __nv_bfloat16 l0 = __float2bfloat16(v0 - __bfloat162float(h0));
                    __nv_bfloat16 l1 = __float2bfloat16(v1 - __bfloat162float(h1));
                    size_t base = (size_t)r * strideCs + cidx;
                    *(uint32_t*)(Cs + base)     = pk2(h0, h1);
                    *(uint32_t*)(Cs + base + N) = pk2(l0, l1);
                } else if (EPI == 3) {
                    *(uint32_t*)(Cs + (size_t)r * N + cidx) = pk2f(v0, v1);
                } else {
                    *(float2*)(C + (size_t)r * N + cidx) = make_float2(v0, v1);
                }
            }
        }
    }
}

// ================= HMMA flash attention =================
// 128 q-rows / CTA, 8 warps x 16 rows, 64-key blocks, double-buffered K/V.
// Q,K,V bf16 [M,512]; output: split hi|lo bf16 ctx, row stride SAE.
#define AST 72   // smem row stride (bf16) = 144B -> ldmatrix conflict-free

__global__ __launch_bounds__(256, 2) void attn_mma(
    const __nv_bfloat16* __restrict__ Q, const __nv_bfloat16* __restrict__ K,
    const __nv_bfloat16* __restrict__ V, __nv_bfloat16* __restrict__ Os)
{
    extern __shared__ __nv_bfloat16 smem[];
    const uint32_t sQ = smem_u32(smem);                       // 128*72
    const uint32_t sK0 = sQ + 128 * AST * 2;                  // 64*72 each
    const uint32_t sV0 = sK0 + 64 * AST * 2;
    const uint32_t sK1 = sV0 + 64 * AST * 2;
    const uint32_t sV1 = sK1 + 64 * AST * 2;

    const int tid = threadIdx.x;
    const int wid = tid >> 5, lid = tid & 31;
    const int g = lid >> 2, tig = lid & 3;
    const int h = blockIdx.y, b = blockIdx.z;
    const int q0 = blockIdx.x * 128;

    const __nv_bfloat16* Qg = Q + ((size_t)(b * SS + q0)) * EE + h * DD;
    const __nv_bfloat16* Kg = K + ((size_t)(b * SS)) * EE + h * DD;
    const __nv_bfloat16* Vg = V + ((size_t)(b * SS)) * EE + h * DD;

    #pragma unroll
    for (int i = 0; i < 4; i++) {
        int idx = tid + i * 256;
        int row = idx >> 3, c8 = (idx & 7) * 8;
        cpasync16(sQ + (uint32_t)(row * AST + c8) * 2, Qg + (size_t)row * EE + c8);
    }

    #define KV_ISSUE(kt, kbuf, vbuf) do {                                   \
        int base_ = (kt) * 64;                                              \
        _Pragma("unroll")                                                   \
        for (int i_ = 0; i_ < 2; i_++) {                                    \
            int idx_ = tid + i_ * 256;                                      \
            int row_ = idx_ >> 3, c8_ = (idx_ & 7) * 8;                     \
            cpasync16((kbuf) + (uint32_t)(row_ * AST + c8_) * 2,            \
                      Kg + (size_t)(base_ + row_) * EE + c8_);              \
            cpasync16((vbuf) + (uint32_t)(row_ * AST + c8_) * 2,            \
                      Vg + (size_t)(base_ + row_) * EE + c8_);              \
        }                                                                   \
        cp_commit();                                                        \
    } while (0)

    KV_ISSUE(0, sK0, sV0);

    float m_run[2] = {-1e30f, -1e30f}, l_run[2] = {0.f, 0.f};
    float oacc[8][4];
    #pragma unroll
    for (int nt = 0; nt < 8; nt++)
        #pragma unroll
        for (int q = 0; q < 4; q++) oacc[nt][q] = 0.f;

    uint32_t qfr[4][4];

    for (int kt = 0; kt < SS / 64; kt++) {
        const int buf = kt & 1;
        const uint32_t kb = buf ? sK1 : sK0;
        const uint32_t vb = buf ? sV1 : sV0;
        if (kt + 1 < SS / 64) {
            const uint32_t nk = buf ? sK0 : sK1;
            const uint32_t nv = buf ? sV0 : sV1;
            KV_ISSUE(kt + 1, nk, nv);
            asm volatile("cp.async.wait_group 1;" ::: "memory");
        } else {
            asm volatile("cp.async.wait_group 0;" ::: "memory");
        }
        __syncthreads();

        if (kt == 0) {
            #pragma unroll
            for (int ks = 0; ks < 4; ks++) {
                uint32_t addr = sQ +
                    (uint32_t)((wid * 16 + (lid & 15)) * AST + ks * 16 + (lid >> 4) * 8) * 2;
                ldm_x4(qfr[ks], addr);
            }
        }

        // ---- S = Q @ K^T ----
        float sfr[8][4];
        #pragma unroll
        for (int nt = 0; nt < 8; nt++)
            #pragma unroll
            for (int q = 0; q < 4; q++) sfr[nt][q] = 0.f;

        const int grp = lid >> 3;
        #pragma unroll
        for (int ks = 0; ks < 4; ks++) {
            uint32_t bfr[4][4];
            #pragma unroll
            for (int q = 0; q < 4; q++) {
                const int n = q * 16 + (grp >> 1) * 8 + (lid & 7);
                uint32_t addr = kb + (uint32_t)(n * AST + ks * 16 + (grp & 1) * 8) * 2;
                ldm_x4(bfr[q], addr);
            }
            #pragma unroll
            for (int nt = 0; nt < 8; nt++)
                mma_bf16(sfr[nt], qfr[ks],
                         bfr[nt >> 1][(nt & 1) * 2],
                         bfr[nt >> 1][(nt & 1) * 2 + 1]);
        }

        // ---- online softmax ----
        #pragma unroll
        for (int half = 0; half < 2; half++) {
            float mloc = -1e30f;
            #pragma unroll
            for (int nt = 0; nt < 8; nt++) {
                sfr[nt][half*2]   *= 0.125f;
                sfr[nt][half*2+1] *= 0.125f;
                mloc = fmaxf(mloc, fmaxf(sfr[nt][half*2], sfr[nt][half*2+1]));
            }
            mloc = fmaxf(mloc, __shfl_xor_sync(0xffffffffu, mloc, 1));
            mloc = fmaxf(mloc, __shfl_xor_sync(0xffffffffu, mloc, 2));
            float m_new = fmaxf(m_run[half], mloc);
            float corr = __expf(m_run[half] - m_new);
            m_run[half] = m_new;
            float lsum = 0.f;
            #pragma unroll
            for (int nt = 0; nt < 8; nt++) {
                float p0 = __expf(sfr[nt][half*2]   - m_new);
                float p1 = __expf(sfr[nt][half*2+1] - m_new);
                sfr[nt][half*2] = p0; sfr[nt][half*2+1] = p1;
                lsum += p0 + p1;
            }
            lsum += __shfl_xor_sync(0xffffffffu, lsum, 1);
            lsum += __shfl_xor_sync(0xffffffffu, lsum, 2);
            l_run[half] = l_run[half] * corr + lsum;
            #pragma unroll
            for (int nt = 0; nt < 8; nt++) {
                oacc[nt][half*2]   *= corr;
                oacc[nt][half*2+1] *= corr;
            }
        }

        // ---- O += P @ V ----
        #pragma unroll
        for (int j = 0; j < 4; j++) {
            uint32_t pfr[4];
            pfr[0] = pk2f(sfr[2*j][0],   sfr[2*j][1]);
            pfr[1] = pk2f(sfr[2*j][2],   sfr[2*j][3]);
            pfr[2] = pk2f(sfr[2*j+1][0], sfr[2*j+1][1]);
            pfr[3] = pk2f(sfr[2*j+1][2], sfr[2*j+1][3]);
            #pragma unroll
            for (int dp = 0; dp < 4; dp++) {
                uint32_t vfr[4];
                uint32_t addr = vb +
                    (uint32_t)((j * 16 + (lid & 15)) * AST + dp * 16 + (lid >> 4) * 8) * 2;
                ldm_x4_t(vfr, addr);
                mma_bf16(oacc[dp*2],     pfr, vfr[0], vfr[1]);
                mma_bf16(oacc[dp*2 + 1], pfr, vfr[2], vfr[3]);
            }
        }
        __syncthreads();
    }
    #undef KV_ISSUE

    // ---- epilogue: split hi|lo ctx (row stride SAE) ----
    const size_t rowBase = (size_t)(b * SS + q0);
    #pragma unroll
    for (int half = 0; half < 2; half++) {
        float inv = 1.0f / l_run[half];
        size_t m = rowBase + wid * 16 + g + half * 8;
        size_t base = m * SAE + h * DD + tig * 2;
        #pragma unroll
        for (int nt = 0; nt < 8; nt++) {
            float o0 = oacc[nt][half*2]     * inv;
            float o1 = oacc[nt][half*2 + 1] * inv;
            __nv_bfloat16 h0 = __float2bfloat16(o0);
            __nv_bfloat16 h1 = __float2bfloat16(o1);
            __nv_bfloat16 l0 = __float2bfloat16(o0 - __bfloat162float(h0));
            __nv_bfloat16 l1 = __float2bfloat16(o1 - __bfloat162float(h1));
            size_t off = base + nt * 8;
            *(uint32_t*)(Os + off)      = pk2(h0, h1);
            *(uint32_t*)(Os + off + EE) = pk2(l0, l1);
        }
    }
}

// ================= split / prep kernels =================
// activation split: x[M,512] fp32 -> xs rows (stride SAE) as [hi | lo]
__global__ __launch_bounds__(256) void split_act(
    const float* __restrict__ x, __nv_bfloat16* __restrict__ xs)
{
    int idx = blockIdx.x * 256 + threadIdx.x;
    int m = idx >> 9, k = idx & 511;
    float v = x[idx];
    __nv_bfloat16 h = __float2bfloat16(v);
    __nv_bfloat16 l = __float2bfloat16(v - __bfloat162float(h));
    size_t base = (size_t)m * SAE;
    xs[base + k] = h; xs[base + EE + k] = l;
}

// weight split+transpose: W[K,N] fp32 -> Ws[N,3K] bf16 as [hi | hi | lo]
__global__ void split_wt(const float* __restrict__ W,
                         __nv_bfloat16* __restrict__ Ws, int K, int N)
{
    __shared__ float t[32][33];
    int n0 = blockIdx.x * 32, k0 = blockIdx.y * 32;
    for (int i = threadIdx.y; i < 32; i += 8)
        t[i][threadIdx.x] = W[(size_t)(k0 + i) * N + n0 + threadIdx.x];
    __syncthreads();
    for (int i = threadIdx.y; i < 32; i += 8) {
        int n = n0 + i, k = k0 + threadIdx.x;
        float v = t[threadIdx.x][i];
        __nv_bfloat16 h = __float2bfloat16(v);
        __nv_bfloat16 l = __float2bfloat16(v - __bfloat162float(h));
        size_t base = (size_t)n * 3 * K + k;
        Ws[base] = h; Ws[base + K] = h; Ws[base + 2*K] = l;
    }
}

// ---------------- layernorm (optional split bf16 out, stride SAE) ----------------
__global__ __launch_bounds__(256) void ln_kernel(
    const float* __restrict__ x, const float* __restrict__ g,
    const float* __restrict__ be, float* __restrict__ y,
    __nv_bfloat16* __restrict__ ys)
{
    __shared__ float red[16];
    const int row = blockIdx.x;
    const int tid = threadIdx.x;
    const float* xr = x + (size_t)row * EE;

    float v0 = xr[tid], v1 = xr[tid + 256];
    float s  = v0 + v1;
    float ss = v0*v0 + v1*v1;
    #pragma unroll
    for (int off = 16; off > 0; off >>= 1) {
        s  += __shfl_xor_sync(0xffffffffu, s,  off);
        ss += __shfl_xor_sync(0xffffffffu, ss, off);
    }
    int wid = tid >> 5, lid = tid & 31;
    if (lid == 0) { red[wid] = s; red[wid + 8] = ss; }
    __syncthreads();
    if (tid < 32) {
        float a = (tid < 8)  ? red[tid]     : 0.f;
        float c = (tid < 8)  ? red[tid + 8] : 0.f;
        #pragma unroll
        for (int off = 4; off > 0; off >>= 1) {
            a += __shfl_xor_sync(0xffffffffu, a, off);
            c += __shfl_xor_sync(0xffffffffu, c, off);
        }
        if (tid == 0) { red[0] = a; red[1] = c; }
    }
    __syncthreads();
    float mean = red[0] * (1.0f / EE);
    float var  = fmaxf(red[1] * (1.0f / EE) - mean * mean, 0.f);
    float rstd = rsqrtf(var + LN_EPS);

    float o0 = (v0 - mean) * rstd * g[tid]       + be[tid];
    float o1 = (v1 - mean) * rstd * g[tid + 256] + be[tid + 256];
    float* yr = y + (size_t)row * EE;
    yr[tid] = o0; yr[tid + 256] = o1;

    if (ys) {
        size_t base = (size_t)row * SAE;
        __nv_bfloat16 h0 = __float2bfloat16(o0);
        __nv_bfloat16 h1 = __float2bfloat16(o1);
        __nv_bfloat16 q0 = __float2bfloat16(o0 - __bfloat162float(h0));
        __nv_bfloat16 q1 = __float2bfloat16(o1 - __bfloat162float(h1));
        ys[base + tid]        = h0;  ys[base + tid + 256]        = h1;
        ys[base + EE + tid]   = q0;  ys[base + EE + tid + 256]   = q1;
    }
}

// ---------------- launch ----------------
extern "C" void kernel_launch(void* const* d_in, const int* in_sizes, int n_in,
                              void* d_out, int out_size)
{
    (void)in_sizes; (void)n_in; (void)out_size;
    const float* query = (const float*)d_in[0];
    const float* key_t = (const float*)d_in[1];
    const float* value = (const float*)d_in[2];
    const float* Wq = (const float*)d_in[3];  const float* bq = (const float*)d_in[4];
    const float* Wk = (const float*)d_in[5];  const float* bk = (const float*)d_in[6];
    const float* Wv = (const float*)d_in[7];  const float* bv = (const float*)d_in[8];
    const float* Wo = (const float*)d_in[9];  const float* bo = (const float*)d_in[10];
    const float* g1 = (const float*)d_in[11]; const float* be1 = (const float*)d_in[12];
    const float* g2 = (const float*)d_in[13]; const float* be2 = (const float*)d_in[14];
    const float* W1 = (const float*)d_in[15]; const float* b1 = (const float*)d_in[16];
    const float* W2 = (const float*)d_in[17]; const float* b2 = (const float*)d_in[18];
    float* out = (float*)d_out;

    void *pQ, *pK, *pV, *pTmp, *pX1, *pA, *pB, *pW;
    cudaGetSymbolAddress(&pQ,   g_Qb);
    cudaGetSymbolAddress(&pK,   g_Kb);
    cudaGetSymbolAddress(&pV,   g_Vb);
    cudaGetSymbolAddress(&pTmp, g_tmp);
    cudaGetSymbolAddress(&pX1,  g_x1);
    cudaGetSymbolAddress(&pA,   g_actA);
    cudaGetSymbolAddress(&pB,   g_actB);
    cudaGetSymbolAddress(&pW,   g_ws);
    __nv_bfloat16* bQ = (__nv_bfloat16*)pQ;
    __nv_bfloat16* bK = (__nv_bfloat16*)pK;
    __nv_bfloat16* bV = (__nv_bfloat16*)pV;
    float* fT = (float*)pTmp; float* fX = (float*)pX1;
    __nv_bfloat16* actA = (__nv_bfloat16*)pA;
    __nv_bfloat16* actB = (__nv_bfloat16*)pB;
    __nv_bfloat16* ws   = (__nv_bfloat16*)pW;

    const int ATTN_SMEM = (128 * AST + 4 * 64 * AST) * 2;  // 55296 bytes
    cudaFuncSetAttribute(attn_mma,
                         cudaFuncAttributeMaxDynamicSharedMemorySize, ATTN_SMEM);

    dim3 gE(EE / 128, MM / 128);          // (4, 64)
    dim3 gF(FF / 128, MM / 128);          // (16, 64)
    dim3 wEE(EE / 32, EE / 32), wEF(FF / 32, EE / 32), wFE(EE / 32, FF / 32);
    dim3 wblk(32, 8);
    int splitBlocks = MM * EE / 256;

    // QKV projections -> bf16 outputs
    split_act<<<splitBlocks, 256>>>(query, actA);
    split_wt<<<wEE, wblk>>>(Wq, ws, EE, EE);
    mma_gemm<3><<<gE, 256>>>(actA, ws, bq, nullptr, nullptr, bQ, EE, K2E, K3E, SAE, 0);
    split_act<<<splitBlocks, 256>>>(key_t, actA);
    split_wt<<<wEE, wblk>>>(Wk, ws, EE, EE);
    mma_gemm<3><<<gE, 256>>>(actA, ws, bk, nullptr, nullptr, bK, EE, K2E, K3E, SAE, 0);
    split_act<<<splitBlocks, 256>>>(value, actA);
    split_wt<<<wEE, wblk>>>(Wv, ws, EE, EE);
    mma_gemm<3><<<gE, 256>>>(actA, ws, bv, nullptr, nullptr, bV, EE, K2E, K3E, SAE, 0);

    // HMMA flash attention -> split ctx in actA (stride SAE)
    attn_mma<<<dim3(SS / 128, HH, BB), 256, ATTN_SMEM>>>(bQ, bK, bV, actA);

    // O projection + residual(query)
    split_wt<<<wEE, wblk>>>(Wo, ws, EE, EE);
    mma_gemm<1><<<gE, 256>>>(actA, ws, bo, query, fT, nullptr, EE, K2E, K3E, SAE, 0);
    // LN1 -> x1 fp32 + split in actA (stride SAE)
    ln_kernel<<<MM, 256>>>(fT, g1, be1, fX, actA);
    // FFN1 + exact GELU -> split output in actB (stride SAF)
    split_wt<<<wEF, wblk>>>(W1, ws, EE, FF);
    mma_gemm<2><<<gF, 256>>>(actA, ws, b1, nullptr, nullptr, actB, FF, K2E, K3E, SAE, SAF);
    // FFN2 + residual(x1)
    split_wt<<<wFE, wblk>>>(W2, ws, FF, EE);
    mma_gemm<1><<<gE, 256>>>(actB, ws, b2, fX, fT, nullptr, EE, K2F, K3F, SAF, 0);
    // LN2 -> out
    ln_kernel<<<MM, 256>>>(fT, g2, be2, out, nullptr);
}

// round 12
// speedup vs baseline: 1.0613x; 1.0613x over previous
#include <cuda_runtime.h>
#include <cuda_bf16.h>
#include <math.h>
#include <stdint.h>

// Problem dims (fixed)
#define BB 4
#define SS 2048
#define EE 512
#define HH 8
#define DD 64
#define FF 2048
#define MM (BB*SS)          // 8192 tokens
#define LN_EPS 1e-5f
#define K3E (3*EE)          // 1536
#define K3F (3*FF)          // 6144

// ---------------- scratch (device globals; no allocation) ----------------
__device__ __nv_bfloat16 g_Qb[(size_t)MM*EE];
__device__ __nv_bfloat16 g_Kb[(size_t)MM*EE];
__device__ __nv_bfloat16 g_Vb[(size_t)MM*EE];
__device__ float g_tmp[MM*EE];
__device__ float g_x1 [MM*EE];
__device__ __nv_bfloat16 g_actA[(size_t)MM*K3E];   // split activations (hi|lo|hi)
__device__ __nv_bfloat16 g_actB[(size_t)MM*K3F];   // split FFN1 output (hi|lo|hi)
__device__ __nv_bfloat16 g_ws  [(size_t)FF*K3E];   // split weights (hi|hi|lo)

// ================= helpers =================
__device__ __forceinline__ uint32_t smem_u32(const void* p) {
    uint32_t a;
    asm("{ .reg .u64 t; cvta.to.shared.u64 t, %1; cvt.u32.u64 %0, t; }"
        : "=r"(a) : "l"(p));
    return a;
}
__device__ __forceinline__ void cpasync16(uint32_t s, const void* g) {
    asm volatile("cp.async.cg.shared.global [%0], [%1], 16;" :: "r"(s), "l"(g));
}
__device__ __forceinline__ void cp_commit() {
    asm volatile("cp.async.commit_group;" ::: "memory");
}
__device__ __forceinline__ void ldm_x4(uint32_t* r, uint32_t addr) {
    asm volatile("ldmatrix.sync.aligned.m8n8.x4.shared.b16 {%0,%1,%2,%3}, [%4];"
        : "=r"(r[0]), "=r"(r[1]), "=r"(r[2]), "=r"(r[3]) : "r"(addr));
}
__device__ __forceinline__ void ldm_x4_t(uint32_t* r, uint32_t addr) {
    asm volatile("ldmatrix.sync.aligned.m8n8.x4.trans.shared.b16 {%0,%1,%2,%3}, [%4];"
        : "=r"(r[0]), "=r"(r[1]), "=r"(r[2]), "=r"(r[3]) : "r"(addr));
}
__device__ __forceinline__ void mma_bf16(float* c, const uint32_t* a,
                                         uint32_t b0, uint32_t b1) {
    asm volatile(
        "mma.sync.aligned.m16n8k16.row.col.f32.bf16.bf16.f32 "
        "{%0,%1,%2,%3}, {%4,%5,%6,%7}, {%8,%9}, {%0,%1,%2,%3};"
        : "+f"(c[0]), "+f"(c[1]), "+f"(c[2]), "+f"(c[3])
        : "r"(a[0]), "r"(a[1]), "r"(a[2]), "r"(a[3]), "r"(b0), "r"(b1));
}
__device__ __forceinline__ uint32_t pk2(__nv_bfloat16 a, __nv_bfloat16 b) {
    __nv_bfloat162 t = __halves2bfloat162(a, b);
    return *reinterpret_cast<uint32_t*>(&t);
}
__device__ __forceinline__ uint32_t pk2f(float a, float b) {
    return pk2(__float2bfloat16(a), __float2bfloat16(b));
}

// ================= HMMA (mma.sync) GEMM =================
// C[M,N] = A'[M,K3] @ B'[N,K3]^T  (bf16x3 split operands, fp32 accum)
// A stored [hi|lo|hi], B stored [hi|hi|lo].
// EPI: 1 = +bias+res fp32 ; 2 = gelu(+bias) -> split(hi|lo|hi) bf16 ;
//      3 = +bias -> plain bf16
// Tile 128x128, BK=32, 8 warps (4m x 2n).
// 3-stage cp.async pipeline (prefetch distance 2), 1 barrier/iter, regs unclamped.
#define SROW 40
#define STAGE_B (2 * 128 * SROW * 2)     // A+B per stage = 20480 bytes
#define GEMM_SMEM (3 * STAGE_B)          // 61440 bytes

template<int EPI>
__global__ __launch_bounds__(256) void mma_gemm(
    const __nv_bfloat16* __restrict__ A, const __nv_bfloat16* __restrict__ Bw,
    const float* __restrict__ bias, const float* __restrict__ res,
    float* __restrict__ C, __nv_bfloat16* __restrict__ Cs,
    int N, int K3)
{
    extern __shared__ __nv_bfloat16 dsm[];
    const uint32_t sBase = smem_u32(dsm);  // stage s: A at s*STAGE_B, B at +10240

    const int tid = threadIdx.x;
    const int wid = tid >> 5, lid = tid & 31;
    const int warp_m = wid & 3;
    const int warp_n = wid >> 2;
    const int m0 = blockIdx.y * 128;
    const int n0 = blockIdx.x * 128;

    float acc[2][8][4];
    #pragma unroll
    for (int mt = 0; mt < 2; mt++)
        #pragma unroll
        for (int nt = 0; nt < 8; nt++)
            #pragma unroll
            for (int q = 0; q < 4; q++) acc[mt][nt][q] = 0.f;

    const int nK = K3 / 32;

    const int r0c = tid >> 2, c0c = (tid & 3);
    const int r1c = (tid + 256) >> 2, c1c = ((tid + 256) & 3);
    const uint32_t so0 = (uint32_t)(r0c * SROW + c0c * 8) * 2;
    const uint32_t so1 = (uint32_t)(r1c * SROW + c1c * 8) * 2;

    #define ISSUE(kt, st) do {                                                  \
        const __nv_bfloat16* Ag = A + (size_t)m0 * K3 + (size_t)(kt) * 32;      \
        const __nv_bfloat16* Bg = Bw + (size_t)n0 * K3 + (size_t)(kt) * 32;     \
        uint32_t _a = sBase + (uint32_t)(st) * STAGE_B;                         \
        uint32_t _b = _a + 10240u;                                              \
        cpasync16(_a + so0, Ag + (size_t)r0c * K3 + c0c * 8);                   \
        cpasync16(_a + so1, Ag + (size_t)r1c * K3 + c1c * 8);                   \
        cpasync16(_b + so0, Bg + (size_t)r0c * K3 + c0c * 8);                   \
        cpasync16(_b + so1, Bg + (size_t)r1c * K3 + c1c * 8);                   \
        cp_commit();                                                            \
    } while (0)

    ISSUE(0, 0);
    ISSUE(1, 1);

    int stC = 0;   // compute stage
    int stI = 2;   // next stage to fill

    for (int kt = 0; kt < nK; kt++) {
        if (kt < nK - 1) {
            asm volatile("cp.async.wait_group 1;" ::: "memory");
        } else {
            asm volatile("cp.async.wait_group 0;" ::: "memory");
        }
        // All warps finished computing iter kt-1 -> safe to overwrite its buffer.
        __syncthreads();
        if (kt + 2 < nK) {
            ISSUE(kt + 2, stI);
            stI = (stI == 2) ? 0 : stI + 1;
        }

        const uint32_t sAb = sBase + (uint32_t)stC * STAGE_B;
        const uint32_t sBb = sAb + 10240u;
        stC = (stC == 2) ? 0 : stC + 1;

        #pragma unroll
        for (int ks = 0; ks < 2; ks++) {
            const int kof = ks * 16;
            uint32_t afr[2][4];
            #pragma unroll
            for (int mt = 0; mt < 2; mt++) {
                uint32_t addr = sAb +
                    (uint32_t)((warp_m * 32 + mt * 16 + (lid & 15)) * SROW
                               + kof + (lid >> 4) * 8) * 2;
                ldm_x4(afr[mt], addr);
            }
            uint32_t bfr[4][4];
            #pragma unroll
            for (int q = 0; q < 4; q++) {
                const int grp = lid >> 3;
                const int n = warp_n * 64 + q * 16 + (grp >> 1) * 8 + (lid & 7);
                uint32_t addr = sBb +
                    (uint32_t)(n * SROW + kof + (grp & 1) * 8) * 2;
                ldm_x4(bfr[q], addr);
            }
            #pragma unroll
            for (int mt = 0; mt < 2; mt++)
                #pragma unroll
                for (int nt = 0; nt < 8; nt++)
                    mma_bf16(acc[mt][nt], afr[mt],
                             bfr[nt >> 1][(nt & 1) * 2],
                             bfr[nt >> 1][(nt & 1) * 2 + 1]);
        }
    }
    #undef ISSUE

    // ---- epilogue (direct from fragments) ----
    const int g = lid >> 2, tig = lid & 3;
    const int row_base = m0 + warp_m * 32;
    const int col_base = n0 + warp_n * 64;
    #pragma unroll
    for (int mt = 0; mt < 2; mt++) {
        #pragma unroll
        for (int half = 0; half < 2; half++) {
            const int r = row_base + mt * 16 + g + half * 8;
            #pragma unroll
            for (int nt = 0; nt < 8; nt++) {
                const int cidx = col_base + nt * 8 + tig * 2;
                float v0 = acc[mt][nt][half * 2 + 0] + bias[cidx];
                float v1 = acc[mt][nt][half * 2 + 1] + bias[cidx + 1];
                if (EPI == 1) {
                    const float2 rv = *(const float2*)(res + (size_t)r * N + cidx);
                    v0 += rv.x; v1 += rv.y;
                }
                if (EPI == 2) {
                    v0 = 0.5f * v0 * (1.0f + erff(v0 * 0.70710678118654752f));
                    v1 = 0.5f * v1 * (1.0f + erff(v1 * 0.70710678118654752f));
                    __nv_bfloat16 h0 = __float2bfloat16(v0);
                    __nv_bfloat16 h1 = __float2bfloat16(v1);
                    __nv_bfloat16 l0 = __float2bfloat16(v0 - __bfloat162float(h0));
                    __nv_bfloat16 l1 = __float2bfloat16(v1 - __bfloat162float(h1));
                    size_t base = (size_t)r * (3 * N) + cidx;
                    *(uint32_t*)(Cs + base)         = pk2(h0, h1);
                    *(uint32_t*)(Cs + base + N)     = pk2(l0, l1);
                    *(uint32_t*)(Cs + base + 2 * N) = pk2(h0, h1);
                } else if (EPI == 3) {
                    *(uint32_t*)(Cs + (size_t)r * N + cidx) = pk2f(v0, v1);
                } else {
                    *(float2*)(C + (size_t)r * N + cidx) = make_float2(v0, v1);
                }
            }
        }
    }
}

// ================= HMMA flash attention =================
// 128 q-rows / CTA, 8 warps x 16 rows, 64-key blocks, double-buffered K/V.
// Q,K,V bf16 [M,512]; output: split hi|lo|hi bf16 ctx [M, 1536].
#define AST 72   // smem row stride (bf16) = 144B -> ldmatrix conflict-free

__global__ __launch_bounds__(256, 2) void attn_mma(
    const __nv_bfloat16* __restrict__ Q, const __nv_bfloat16* __restrict__ K,
    const __nv_bfloat16* __restrict__ V, __nv_bfloat16* __restrict__ Os)
{
    extern __shared__ __nv_bfloat16 smem[];
    const uint32_t sQ = smem_u32(smem);                       // 128*72
    const uint32_t sK0 = sQ + 128 * AST * 2;                  // 64*72 each
    const uint32_t sV0 = sK0 + 64 * AST * 2;
    const uint32_t sK1 = sV0 + 64 * AST * 2;
    const uint32_t sV1 = sK1 + 64 * AST * 2;

    const int tid = threadIdx.x;
    const int wid = tid >> 5, lid = tid & 31;
    const int g = lid >> 2, tig = lid & 3;
    const int h = blockIdx.y, b = blockIdx.z;
    const int q0 = blockIdx.x * 128;

    const __nv_bfloat16* Qg = Q + ((size_t)(b * SS + q0)) * EE + h * DD;
    const __nv_bfloat16* Kg = K + ((size_t)(b * SS)) * EE + h * DD;
    const __nv_bfloat16* Vg = V + ((size_t)(b * SS)) * EE + h * DD;

    #pragma unroll
    for (int i = 0; i < 4; i++) {
        int idx = tid + i * 256;
        int row = idx >> 3, c8 = (idx & 7) * 8;
        cpasync16(sQ + (uint32_t)(row * AST + c8) * 2, Qg + (size_t)row * EE + c8);
    }

    #define KV_ISSUE(kt, kbuf, vbuf) do {                                   \
        int base_ = (kt) * 64;                                              \
        _Pragma("unroll")                                                   \
        for (int i_ = 0; i_ < 2; i_++) {                                    \
            int idx_ = tid + i_ * 256;                                      \
            int row_ = idx_ >> 3, c8_ = (idx_ & 7) * 8;                     \
            cpasync16((kbuf) + (uint32_t)(row_ * AST + c8_) * 2,            \
                      Kg + (size_t)(base_ + row_) * EE + c8_);              \
            cpasync16((vbuf) + (uint32_t)(row_ * AST + c8_) * 2,            \
                      Vg + (size_t)(base_ + row_) * EE + c8_);              \
        }                                                                   \
        cp_commit();                                                        \
    } while (0)

    KV_ISSUE(0, sK0, sV0);

    float m_run[2] = {-1e30f, -1e30f}, l_run[2] = {0.f, 0.f};
    float oacc[8][4];
    #pragma unroll
    for (int nt = 0; nt < 8; nt++)
        #pragma unroll
        for (int q = 0; q < 4; q++) oacc[nt][q] = 0.f;

    uint32_t qfr[4][4];

    for (int kt = 0; kt < SS / 64; kt++) {
        const int buf = kt & 1;
        const uint32_t kb = buf ? sK1 : sK0;
        const uint32_t vb = buf ? sV1 : sV0;
        if (kt + 1 < SS / 64) {
            const uint32_t nk = buf ? sK0 : sK1;
            const uint32_t nv = buf ? sV0 : sV1;
            KV_ISSUE(kt + 1, nk, nv);
            asm volatile("cp.async.wait_group 1;" ::: "memory");
        } else {
            asm volatile("cp.async.wait_group 0;" ::: "memory");
        }
        __syncthreads();

        if (kt == 0) {
            #pragma unroll
            for (int ks = 0; ks < 4; ks++) {
                uint32_t addr = sQ +
                    (uint32_t)((wid * 16 + (lid & 15)) * AST + ks * 16 + (lid >> 4) * 8) * 2;
                ldm_x4(qfr[ks], addr);
            }
        }

        // ---- S = Q @ K^T ----
        float sfr[8][4];
        #pragma unroll
        for (int nt = 0; nt < 8; nt++)
            #pragma unroll
            for (int q = 0; q < 4; q++) sfr[nt][q] = 0.f;

        const int grp = lid >> 3;
        #pragma unroll
        for (int ks = 0; ks < 4; ks++) {
            uint32_t bfr[4][4];
            #pragma unroll
            for (int q = 0; q < 4; q++) {
                const int n = q * 16 + (grp >> 1) * 8 + (lid & 7);
                uint32_t addr = kb + (uint32_t)(n * AST + ks * 16 + (grp & 1) * 8) * 2;
                ldm_x4(bfr[q], addr);
            }
            #pragma unroll
            for (int nt = 0; nt < 8; nt++)
                mma_bf16(sfr[nt], qfr[ks],
                         bfr[nt >> 1][(nt & 1) * 2],
                         bfr[nt >> 1][(nt & 1) * 2 + 1]);
        }

        // ---- online softmax ----
        #pragma unroll
        for (int half = 0; half < 2; half++) {
            float mloc = -1e30f;
            #pragma unroll
            for (int nt = 0; nt < 8; nt++) {
                sfr[nt][half*2]   *= 0.125f;
                sfr[nt][half*2+1] *= 0.125f;
                mloc = fmaxf(mloc, fmaxf(sfr[nt][half*2], sfr[nt][half*2+1]));
            }
            mloc = fmaxf(mloc, __shfl_xor_sync(0xffffffffu, mloc, 1));
            mloc = fmaxf(mloc, __shfl_xor_sync(0xffffffffu, mloc, 2));
            float m_new = fmaxf(m_run[half], mloc);
            float corr = __expf(m_run[half] - m_new);
            m_run[half] = m_new;
            float lsum = 0.f;
            #pragma unroll
            for (int nt = 0; nt < 8; nt++) {
                float p0 = __expf(sfr[nt][half*2]   - m_new);
                float p1 = __expf(sfr[nt][half*2+1] - m_new);
                sfr[nt][half*2] = p0; sfr[nt][half*2+1] = p1;
                lsum += p0 + p1;
            }
            lsum += __shfl_xor_sync(0xffffffffu, lsum, 1);
            lsum += __shfl_xor_sync(0xffffffffu, lsum, 2);
            l_run[half] = l_run[half] * corr + lsum;
            #pragma unroll
            for (int nt = 0; nt < 8; nt++) {
                oacc[nt][half*2]   *= corr;
                oacc[nt][half*2+1] *= corr;
            }
        }

        // ---- O += P @ V ----
        #pragma unroll
        for (int j = 0; j < 4; j++) {
            uint32_t pfr[4];
            pfr[0] = pk2f(sfr[2*j][0],   sfr[2*j][1]);
            pfr[1] = pk2f(sfr[2*j][2],   sfr[2*j][3]);
            pfr[2] = pk2f(sfr[2*j+1][0], sfr[2*j+1][1]);
            pfr[3] = pk2f(sfr[2*j+1][2], sfr[2*j+1][3]);
            #pragma unroll
            for (int dp = 0; dp < 4; dp++) {
                uint32_t vfr[4];
                uint32_t addr = vb +
                    (uint32_t)((j * 16 + (lid & 15)) * AST + dp * 16 + (lid >> 4) * 8) * 2;
                ldm_x4_t(vfr, addr);
                mma_bf16(oacc[dp*2],     pfr, vfr[0], vfr[1]);
                mma_bf16(oacc[dp*2 + 1], pfr, vfr[2], vfr[3]);
            }
        }
        __syncthreads();
    }
    #undef KV_ISSUE

    // ---- epilogue: split hi|lo|hi ctx ----
    const size_t rowBase = (size_t)(b * SS + q0);
    #pragma unroll
    for (int half = 0; half < 2; half++) {
        float inv = 1.0f / l_run[half];
        size_t m = rowBase + wid * 16 + g + half * 8;
        size_t base = m * K3E + h * DD + tig * 2;
        #pragma unroll
        for (int nt = 0; nt < 8; nt++) {
            float o0 = oacc[nt][half*2]     * inv;
            float o1 = oacc[nt][half*2 + 1] * inv;
            __nv_bfloat16 h0 = __float2bfloat16(o0);
            __nv_bfloat16 h1 = __float2bfloat16(o1);
            __nv_bfloat16 l0 = __float2bfloat16(o0 - __bfloat162float(h0));
            __nv_bfloat16 l1 = __float2bfloat16(o1 - __bfloat162float(h1));
            size_t off = base + nt * 8;
            *(uint32_t*)(Os + off)          = pk2(h0, h1);
            *(uint32_t*)(Os + off + EE)     = pk2(l0, l1);
            *(uint32_t*)(Os + off + 2*EE)   = pk2(h0, h1);
        }
    }
}

// ================= split / prep kernels =================
// activation split: x[M,512] fp32 -> xs[M,1536] bf16 as [hi | lo | hi]
__global__ __launch_bounds__(256) void split_act(
    const float* __restrict__ x, __nv_bfloat16* __restrict__ xs)
{
    int idx = blockIdx.x * 256 + threadIdx.x;
    int m = idx >> 9, k = idx & 511;
    float v = x[idx];
    __nv_bfloat16 h = __float2bfloat16(v);
    __nv_bfloat16 l = __float2bfloat16(v - __bfloat162float(h));
    size_t base = (size_t)m * K3E;
    xs[base + k] = h; xs[base + EE + k] = l; xs[base + 2*EE + k] = h;
}

// weight split+transpose: W[K,N] fp32 -> Ws[N,3K] bf16 as [hi | hi | lo]
__global__ void split_wt(const float* __restrict__ W,
                         __nv_bfloat16* __restrict__ Ws, int K, int N)
{
    __shared__ float t[32][33];
    int n0 = blockIdx.x * 32, k0 = blockIdx.y * 32;
    for (int i = threadIdx.y; i < 32; i += 8)
        t[i][threadIdx.x] = W[(size_t)(k0 + i) * N + n0 + threadIdx.x];
    __syncthreads();
    for (int i = threadIdx.y; i < 32; i += 8) {
        int n = n0 + i, k = k0 + threadIdx.x;
        float v = t[threadIdx.x][i];
        __nv_bfloat16 h = __float2bfloat16(v);
        __nv_bfloat16 l = __float2bfloat16(v - __bfloat162float(h));
        size_t base = (size_t)n * 3 * K + k;
        Ws[base] = h; Ws[base + K] = h; Ws[base + 2*K] = l;
    }
}

// ---------------- layernorm (optional split bf16 out) ----------------
__global__ __launch_bounds__(256) void ln_kernel(
    const float* __restrict__ x, const float* __restrict__ g,
    const float* __restrict__ be, float* __restrict__ y,
    __nv_bfloat16* __restrict__ ys)
{
    __shared__ float red[16];
    const int row = blockIdx.x;
    const int tid = threadIdx.x;
    const float* xr = x + (size_t)row * EE;

    float v0 = xr[tid], v1 = xr[tid + 256];
    float s  = v0 + v1;
    float ss = v0*v0 + v1*v1;
    #pragma unroll
    for (int off = 16; off > 0; off >>= 1) {
        s  += __shfl_xor_sync(0xffffffffu, s,  off);
        ss += __shfl_xor_sync(0xffffffffu, ss, off);
    }
    int wid = tid >> 5, lid = tid & 31;
    if (lid == 0) { red[wid] = s; red[wid + 8] = ss; }
    __syncthreads();
    if (tid < 32) {
        float a = (tid < 8)  ? red[tid]     : 0.f;
        float c = (tid < 8)  ? red[tid + 8] : 0.f;
        #pragma unroll
        for (int off = 4; off > 0; off >>= 1) {
            a += __shfl_xor_sync(0xffffffffu, a, off);
            c += __shfl_xor_sync(0xffffffffu, c, off);
        }
        if (tid == 0) { red[0] = a; red[1] = c; }
    }
    __syncthreads();
    float mean = red[0] * (1.0f / EE);
    float var  = fmaxf(red[1] * (1.0f / EE) - mean * mean, 0.f);
    float rstd = rsqrtf(var + LN_EPS);

    float o0 = (v0 - mean) * rstd * g[tid]       + be[tid];
    float o1 = (v1 - mean) * rstd * g[tid + 256] + be[tid + 256];
    float* yr = y + (size_t)row * EE;
    yr[tid] = o0; yr[tid + 256] = o1;

    if (ys) {
        size_t base = (size_t)row * K3E;
        __nv_bfloat16 h0 = __float2bfloat16(o0);
        __nv_bfloat16 h1 = __float2bfloat16(o1);
        __nv_bfloat16 q0 = __float2bfloat16(o0 - __bfloat162float(h0));
        __nv_bfloat16 q1 = __float2bfloat16(o1 - __bfloat162float(h1));
        ys[base + tid]            = h0;  ys[base + tid + 256]            = h1;
        ys[base + EE + tid]       = q0;  ys[base + EE + tid + 256]       = q1;
        ys[base + 2*EE + tid]     = h0;  ys[base + 2*EE + tid + 256]     = h1;
    }
}

// ---------------- launch ----------------
extern "C" void kernel_launch(void* const* d_in, const int* in_sizes, int n_in,
                              void* d_out, int out_size)
{
    (void)in_sizes; (void)n_in; (void)out_size;
    const float* query = (const float*)d_in[0];
    const float* key_t = (const float*)d_in[1];
    const float* value = (const float*)d_in[2];
    const float* Wq = (const float*)d_in[3];  const float* bq = (const float*)d_in[4];
    const float* Wk = (const float*)d_in[5];  const float* bk = (const float*)d_in[6];
    const float* Wv = (const float*)d_in[7];  const float* bv = (const float*)d_in[8];
    const float* Wo = (const float*)d_in[9];  const float* bo = (const float*)d_in[10];
    const float* g1 = (const float*)d_in[11]; const float* be1 = (const float*)d_in[12];
    const float* g2 = (const float*)d_in[13]; const float* be2 = (const float*)d_in[14];
    const float* W1 = (const float*)d_in[15]; const float* b1 = (const float*)d_in[16];
    const float* W2 = (const float*)d_in[17]; const float* b2 = (const float*)d_in[18];
    float* out = (float*)d_out;

    void *pQ, *pK, *pV, *pTmp, *pX1, *pA, *pB, *pW;
    cudaGetSymbolAddress(&pQ,   g_Qb);
    cudaGetSymbolAddress(&pK,   g_Kb);
    cudaGetSymbolAddress(&pV,   g_Vb);
    cudaGetSymbolAddress(&pTmp, g_tmp);
    cudaGetSymbolAddress(&pX1,  g_x1);
    cudaGetSymbolAddress(&pA,   g_actA);
    cudaGetSymbolAddress(&pB,   g_actB);
    cudaGetSymbolAddress(&pW,   g_ws);
    __nv_bfloat16* bQ = (__nv_bfloat16*)pQ;
    __nv_bfloat16* bK = (__nv_bfloat16*)pK;
    __nv_bfloat16* bV = (__nv_bfloat16*)pV;
    float* fT = (float*)pTmp; float* fX = (float*)pX1;
    __nv_bfloat16* actA = (__nv_bfloat16*)pA;
    __nv_bfloat16* actB = (__nv_bfloat16*)pB;
    __nv_bfloat16* ws   = (__nv_bfloat16*)pW;

    const int ATTN_SMEM = (128 * AST + 4 * 64 * AST) * 2;  // 55296 bytes
    cudaFuncSetAttribute(attn_mma,
                         cudaFuncAttributeMaxDynamicSharedMemorySize, ATTN_SMEM);
    cudaFuncSetAttribute(mma_gemm<1>,
                         cudaFuncAttributeMaxDynamicSharedMemorySize, GEMM_SMEM);
    cudaFuncSetAttribute(mma_gemm<2>,
                         cudaFuncAttributeMaxDynamicSharedMemorySize, GEMM_SMEM);
    cudaFuncSetAttribute(mma_gemm<3>,
                         cudaFuncAttributeMaxDynamicSharedMemorySize, GEMM_SMEM);

    dim3 gE(EE / 128, MM / 128);          // (4, 64)
    dim3 gF(FF / 128, MM / 128);          // (16, 64)
    dim3 wEE(EE / 32, EE / 32), wEF(FF / 32, EE / 32), wFE(EE / 32, FF / 32);
    dim3 wblk(32, 8);
    int splitBlocks = MM * EE / 256;

    // QKV projections -> bf16 outputs
    split_act<<<splitBlocks, 256>>>(query, actA);
    split_wt<<<wEE, wblk>>>(Wq, ws, EE, EE);
    mma_gemm<3><<<gE, 256, GEMM_SMEM>>>(actA, ws, bq, nullptr, nullptr, bQ, EE, K3E);
    split_act<<<splitBlocks, 256>>>(key_t, actA);
    split_wt<<<wEE, wblk>>>(Wk, ws, EE, EE);
    mma_gemm<3><<<gE, 256, GEMM_SMEM>>>(actA, ws, bk, nullptr, nullptr, bK, EE, K3E);
    split_act<<<splitBlocks, 256>>>(value, actA);
    split_wt<<<wEE, wblk>>>(Wv, ws, EE, EE);
    mma_gemm<3><<<gE, 256, GEMM_SMEM>>>(actA, ws, bv, nullptr, nullptr, bV, EE, K3E);

    // HMMA flash attention -> split ctx in actA
    attn_mma<<<dim3(SS / 128, HH, BB), 256, ATTN_SMEM>>>(bQ, bK, bV, actA);

    // O projection + residual(query)
    split_wt<<<wEE, wblk>>>(Wo, ws, EE, EE);
    mma_gemm<1><<<gE, 256, GEMM_SMEM>>>(actA, ws, bo, query, fT, nullptr, EE, K3E);
    // LN1 -> x1 fp32 + split in actA
    ln_kernel<<<MM, 256>>>(fT, g1, be1, fX, actA);
    // FFN1 + exact GELU -> split output in actB
    split_wt<<<wEF, wblk>>>(W1, ws, EE, FF);
    mma_gemm<2><<<gF, 256, GEMM_SMEM>>>(actA, ws, b1, nullptr, nullptr, actB, FF, K3E);
    // FFN2 + residual(x1)
    split_wt<<<wFE, wblk>>>(W2, ws, FF, EE);
    mma_gemm<1><<<gE, 256, GEMM_SMEM>>>(actB, ws, b2, fX, fT, nullptr, EE, K3F);
    // LN2 -> out
    ln_kernel<<<MM, 256>>>(fT, g2, be2, out, nullptr);
}

// round 14
// speedup vs baseline: 1.4522x; 1.3683x over previous
#include <cuda_runtime.h>
#include <cuda_fp16.h>
#include <math.h>
#include <stdint.h>

// Problem dims (fixed)
#define BB 4
#define SS 2048
#define EE 512
#define HH 8
#define DD 64
#define FF 2048
#define MM (BB*SS)          // 8192 tokens
#define LN_EPS 1e-5f
#define K2E 1024            // 2*512  (fp16 hi|lo split-K for K=512)
#define K2F 4096            // 2*2048 (fp16 hi|lo split-K for K=2048)

// ---------------- scratch (device globals; no allocation) ----------------
__device__ __half g_Qh[(size_t)MM*EE];
__device__ __half g_Kh[(size_t)MM*EE];
__device__ __half g_Vh[(size_t)MM*EE];
__device__ float g_tmp[MM*EE];
__device__ float g_x1 [MM*EE];
__device__ __half g_actA[(size_t)MM*K2E];   // split activations (hi|lo) fp16
__device__ __half g_actB[(size_t)MM*K2F];   // split FFN1 output (hi|lo) fp16
__device__ __half g_ws  [(size_t)FF*K2E];   // weights fp16, duplicated (Wh|Wh)

// ================= helpers =================
__device__ __forceinline__ uint32_t smem_u32(const void* p) {
    uint32_t a;
    asm("{ .reg .u64 t; cvta.to.shared.u64 t, %1; cvt.u32.u64 %0, t; }"
        : "=r"(a) : "l"(p));
    return a;
}
__device__ __forceinline__ void cpasync16(uint32_t s, const void* g) {
    asm volatile("cp.async.cg.shared.global [%0], [%1], 16;" :: "r"(s), "l"(g));
}
__device__ __forceinline__ void cp_commit() {
    asm volatile("cp.async.commit_group;" ::: "memory");
}
__device__ __forceinline__ void ldm_x4(uint32_t* r, uint32_t addr) {
    asm volatile("ldmatrix.sync.aligned.m8n8.x4.shared.b16 {%0,%1,%2,%3}, [%4];"
        : "=r"(r[0]), "=r"(r[1]), "=r"(r[2]), "=r"(r[3]) : "r"(addr));
}
__device__ __forceinline__ void ldm_x4_t(uint32_t* r, uint32_t addr) {
    asm volatile("ldmatrix.sync.aligned.m8n8.x4.trans.shared.b16 {%0,%1,%2,%3}, [%4];"
        : "=r"(r[0]), "=r"(r[1]), "=r"(r[2]), "=r"(r[3]) : "r"(addr));
}
__device__ __forceinline__ void mma_f16(float* c, const uint32_t* a,
                                        uint32_t b0, uint32_t b1) {
    asm volatile(
        "mma.sync.aligned.m16n8k16.row.col.f32.f16.f16.f32 "
        "{%0,%1,%2,%3}, {%4,%5,%6,%7}, {%8,%9}, {%0,%1,%2,%3};"
        : "+f"(c[0]), "+f"(c[1]), "+f"(c[2]), "+f"(c[3])
        : "r"(a[0]), "r"(a[1]), "r"(a[2]), "r"(a[3]), "r"(b0), "r"(b1));
}
__device__ __forceinline__ uint32_t pk2h(__half a, __half b) {
    __half2 t = __halves2half2(a, b);
    return *reinterpret_cast<uint32_t*>(&t);
}
__device__ __forceinline__ uint32_t pk2hf(float a, float b) {
    __half2 t = __floats2half2_rn(a, b);
    return *reinterpret_cast<uint32_t*>(&t);
}

// ================= HMMA (mma.sync) fp16x2 GEMM =================
// C[M,N] = A'[M,K2] @ B'[N,K2]^T  with A' = (Ah|Al), B' = (Bh|Bh):
//   C = Ah@Bh + Al@Bh  (error = A*(B-Bh) ~ 2^-12, fp32 accum)
// EPI: 1 = +bias+res fp32 ; 2 = gelu(+bias) -> split(hi|lo) fp16, stride 2N ;
//      3 = +bias -> plain fp16
// Tile 128x128, BK=32, 8 warps (4m x 2n), 2-stage double buffer (R7 engine).
#define SROW 40

template<int EPI>
__global__ __launch_bounds__(256) void mma_gemm(
    const __half* __restrict__ A, const __half* __restrict__ Bw,
    const float* __restrict__ bias, const float* __restrict__ res,
    float* __restrict__ C, __half* __restrict__ Cs,
    int N, int K2)
{
    __shared__ __half As[2][128 * SROW];
    __shared__ __half Bs[2][128 * SROW];

    const int tid = threadIdx.x;
    const int wid = tid >> 5, lid = tid & 31;
    const int warp_m = wid & 3;
    const int warp_n = wid >> 2;
    const int m0 = blockIdx.y * 128;
    const int n0 = blockIdx.x * 128;

    const uint32_t sA0 = smem_u32(As[0]), sA1 = smem_u32(As[1]);
    const uint32_t sB0 = smem_u32(Bs[0]), sB1 = smem_u32(Bs[1]);

    float acc[2][8][4];
    #pragma unroll
    for (int mt = 0; mt < 2; mt++)
        #pragma unroll
        for (int nt = 0; nt < 8; nt++)
            #pragma unroll
            for (int q = 0; q < 4; q++) acc[mt][nt][q] = 0.f;

    const int nK = K2 / 32;

    const int r0c = tid >> 2, c0c = (tid & 3);
    const int r1c = (tid + 256) >> 2, c1c = ((tid + 256) & 3);
    const uint32_t so0 = (uint32_t)(r0c * SROW + c0c * 8) * 2;
    const uint32_t so1 = (uint32_t)(r1c * SROW + c1c * 8) * 2;

    #define ISSUE(kt, b) do {                                                   \
        const __half* Ag = A + (size_t)m0 * K2 + (size_t)(kt) * 32;             \
        const __half* Bg = Bw + (size_t)n0 * K2 + (size_t)(kt) * 32;            \
        uint32_t _a = (b) ? sA1 : sA0, _b = (b) ? sB1 : sB0;                    \
        cpasync16(_a + so0, Ag + (size_t)r0c * K2 + c0c * 8);                   \
        cpasync16(_a + so1, Ag + (size_t)r1c * K2 + c1c * 8);                   \
        cpasync16(_b + so0, Bg + (size_t)r0c * K2 + c0c * 8);                   \
        cpasync16(_b + so1, Bg + (size_t)r1c * K2 + c1c * 8);                   \
        cp_commit();                                                            \
    } while (0)

    ISSUE(0, 0);

    for (int kt = 0; kt < nK; kt++) {
        const int b = kt & 1;
        if (kt + 1 < nK) {
            ISSUE(kt + 1, b ^ 1);
            asm volatile("cp.async.wait_group 1;" ::: "memory");
        } else {
            asm volatile("cp.async.wait_group 0;" ::: "memory");
        }
        __syncthreads();

        const uint32_t sAb = b ? sA1 : sA0;
        const uint32_t sBb = b ? sB1 : sB0;

        #pragma unroll
        for (int ks = 0; ks < 2; ks++) {
            const int kof = ks * 16;
            uint32_t afr[2][4];
            #pragma unroll
            for (int mt = 0; mt < 2; mt++) {
                uint32_t addr = sAb +
                    (uint32_t)((warp_m * 32 + mt * 16 + (lid & 15)) * SROW
                               + kof + (lid >> 4) * 8) * 2;
                ldm_x4(afr[mt], addr);
            }
            uint32_t bfr[4][4];
            #pragma unroll
            for (int q = 0; q < 4; q++) {
                const int grp = lid >> 3;
                const int n = warp_n * 64 + q * 16 + (grp >> 1) * 8 + (lid & 7);
                uint32_t addr = sBb +
                    (uint32_t)(n * SROW + kof + (grp & 1) * 8) * 2;
                ldm_x4(bfr[q], addr);
            }
            #pragma unroll
            for (int mt = 0; mt < 2; mt++)
                #pragma unroll
                for (int nt = 0; nt < 8; nt++)
                    mma_f16(acc[mt][nt], afr[mt],
                            bfr[nt >> 1][(nt & 1) * 2],
                            bfr[nt >> 1][(nt & 1) * 2 + 1]);
        }
        __syncthreads();
    }
    #undef ISSUE

    // ---- epilogue (direct from fragments) ----
    const int g = lid >> 2, tig = lid & 3;
    const int row_base = m0 + warp_m * 32;
    const int col_base = n0 + warp_n * 64;
    #pragma unroll
    for (int mt = 0; mt < 2; mt++) {
        #pragma unroll
        for (int half = 0; half < 2; half++) {
            const int r = row_base + mt * 16 + g + half * 8;
            #pragma unroll
            for (int nt = 0; nt < 8; nt++) {
                const int cidx = col_base + nt * 8 + tig * 2;
                float v0 = acc[mt][nt][half * 2 + 0] + bias[cidx];
                float v1 = acc[mt][nt][half * 2 + 1] + bias[cidx + 1];
                if (EPI == 1) {
                    const float2 rv = *(const float2*)(res + (size_t)r * N + cidx);
                    v0 += rv.x; v1 += rv.y;
                }
                if (EPI == 2) {
                    v0 = 0.5f * v0 * (1.0f + erff(v0 * 0.70710678118654752f));
                    v1 = 0.5f * v1 * (1.0f + erff(v1 * 0.70710678118654752f));
                    __half h0 = __float2half_rn(v0);
                    __half h1 = __float2half_rn(v1);
                    __half l0 = __float2half_rn(v0 - __half2float(h0));
                    __half l1 = __float2half_rn(v1 - __half2float(h1));
                    size_t base = (size_t)r * (2 * N) + cidx;
                    *(uint32_t*)(Cs + base)     = pk2h(h0, h1);
                    *(uint32_t*)(Cs + base + N) = pk2h(l0, l1);
                } else if (EPI == 3) {
                    *(uint32_t*)(Cs + (size_t)r * N + cidx) = pk2hf(v0, v1);
                } else {
                    *(float2*)(C + (size_t)r * N + cidx) = make_float2(v0, v1);
                }
            }
        }
    }
}

// ================= HMMA flash attention (fp16) =================
// 128 q-rows / CTA, 8 warps x 16 rows, 64-key blocks, double-buffered K/V.
// Q,K,V fp16 [M,512]; output: split hi|lo fp16 ctx [M, K2E].
#define AST 72   // smem row stride (fp16) = 144B -> ldmatrix conflict-free

__global__ __launch_bounds__(256, 2) void attn_mma(
    const __half* __restrict__ Q, const __half* __restrict__ K,
    const __half* __restrict__ V, __half* __restrict__ Os)
{
    extern __shared__ __half smem[];
    const uint32_t sQ = smem_u32(smem);                       // 128*72
    const uint32_t sK0 = sQ + 128 * AST * 2;                  // 64*72 each
    const uint32_t sV0 = sK0 + 64 * AST * 2;
    const uint32_t sK1 = sV0 + 64 * AST * 2;
    const uint32_t sV1 = sK1 + 64 * AST * 2;

    const int tid = threadIdx.x;
    const int wid = tid >> 5, lid = tid & 31;
    const int g = lid >> 2, tig = lid & 3;
    const int h = blockIdx.y, b = blockIdx.z;
    const int q0 = blockIdx.x * 128;

    const __half* Qg = Q + ((size_t)(b * SS + q0)) * EE + h * DD;
    const __half* Kg = K + ((size_t)(b * SS)) * EE + h * DD;
    const __half* Vg = V + ((size_t)(b * SS)) * EE + h * DD;

    #pragma unroll
    for (int i = 0; i < 4; i++) {
        int idx = tid + i * 256;
        int row = idx >> 3, c8 = (idx & 7) * 8;
        cpasync16(sQ + (uint32_t)(row * AST + c8) * 2, Qg + (size_t)row * EE + c8);
    }

    #define KV_ISSUE(kt, kbuf, vbuf) do {                                   \
        int base_ = (kt) * 64;                                              \
        _Pragma("unroll")                                                   \
        for (int i_ = 0; i_ < 2; i_++) {                                    \
            int idx_ = tid + i_ * 256;                                      \
            int row_ = idx_ >> 3, c8_ = (idx_ & 7) * 8;                     \
            cpasync16((kbuf) + (uint32_t)(row_ * AST + c8_) * 2,            \
                      Kg + (size_t)(base_ + row_) * EE + c8_);              \
            cpasync16((vbuf) + (uint32_t)(row_ * AST + c8_) * 2,            \
                      Vg + (size_t)(base_ + row_) * EE + c8_);              \
        }                                                                   \
        cp_commit();                                                        \
    } while (0)

    KV_ISSUE(0, sK0, sV0);

    float m_run[2] = {-1e30f, -1e30f}, l_run[2] = {0.f, 0.f};
    float oacc[8][4];
    #pragma unroll
    for (int nt = 0; nt < 8; nt++)
        #pragma unroll
        for (int q = 0; q < 4; q++) oacc[nt][q] = 0.f;

    uint32_t qfr[4][4];

    for (int kt = 0; kt < SS / 64; kt++) {
        const int buf = kt & 1;
        const uint32_t kb = buf ? sK1 : sK0;
        const uint32_t vb = buf ? sV1 : sV0;
        if (kt + 1 < SS / 64) {
            const uint32_t nk = buf ? sK0 : sK1;
            const uint32_t nv = buf ? sV0 : sV1;
            KV_ISSUE(kt + 1, nk, nv);
            asm volatile("cp.async.wait_group 1;" ::: "memory");
        } else {
            asm volatile("cp.async.wait_group 0;" ::: "memory");
        }
        __syncthreads();

        if (kt == 0) {
            #pragma unroll
            for (int ks = 0; ks < 4; ks++) {
                uint32_t addr = sQ +
                    (uint32_t)((wid * 16 + (lid & 15)) * AST + ks * 16 + (lid >> 4) * 8) * 2;
                ldm_x4(qfr[ks], addr);
            }
        }

        // ---- S = Q @ K^T ----
        float sfr[8][4];
        #pragma unroll
        for (int nt = 0; nt < 8; nt++)
            #pragma unroll
            for (int q = 0; q < 4; q++) sfr[nt][q] = 0.f;

        const int grp = lid >> 3;
        #pragma unroll
        for (int ks = 0; ks < 4; ks++) {
            uint32_t bfr[4][4];
            #pragma unroll
            for (int q = 0; q < 4; q++) {
                const int n = q * 16 + (grp >> 1) * 8 + (lid & 7);
                uint32_t addr = kb + (uint32_t)(n * AST + ks * 16 + (grp & 1) * 8) * 2;
                ldm_x4(bfr[q], addr);
            }
            #pragma unroll
            for (int nt = 0; nt < 8; nt++)
                mma_f16(sfr[nt], qfr[ks],
                        bfr[nt >> 1][(nt & 1) * 2],
                        bfr[nt >> 1][(nt & 1) * 2 + 1]);
        }

        // ---- online softmax ----
        #pragma unroll
        for (int half = 0; half < 2; half++) {
            float mloc = -1e30f;
            #pragma unroll
            for (int nt = 0; nt < 8; nt++) {
                sfr[nt][half*2]   *= 0.125f;
                sfr[nt][half*2+1] *= 0.125f;
                mloc = fmaxf(mloc, fmaxf(sfr[nt][half*2], sfr[nt][half*2+1]));
            }
            mloc = fmaxf(mloc, __shfl_xor_sync(0xffffffffu, mloc, 1));
            mloc = fmaxf(mloc, __shfl_xor_sync(0xffffffffu, mloc, 2));
            float m_new = fmaxf(m_run[half], mloc);
            float corr = __expf(m_run[half] - m_new);
            m_run[half] = m_new;
            float lsum = 0.f;
            #pragma unroll
            for (int nt = 0; nt < 8; nt++) {
                float p0 = __expf(sfr[nt][half*2]   - m_new);
                float p1 = __expf(sfr[nt][half*2+1] - m_new);
                sfr[nt][half*2] = p0; sfr[nt][half*2+1] = p1;
                lsum += p0 + p1;
            }
            lsum += __shfl_xor_sync(0xffffffffu, lsum, 1);
            lsum += __shfl_xor_sync(0xffffffffu, lsum, 2);
            l_run[half] = l_run[half] * corr + lsum;
            #pragma unroll
            for (int nt = 0; nt < 8; nt++) {
                oacc[nt][half*2]   *= corr;
                oacc[nt][half*2+1] *= corr;
            }
        }

        // ---- O += P @ V ----
        #pragma unroll
        for (int j = 0; j < 4; j++) {
            uint32_t pfr[4];
            pfr[0] = pk2hf(sfr[2*j][0],   sfr[2*j][1]);
            pfr[1] = pk2hf(sfr[2*j][2],   sfr[2*j][3]);
            pfr[2] = pk2hf(sfr[2*j+1][0], sfr[2*j+1][1]);
            pfr[3] = pk2hf(sfr[2*j+1][2], sfr[2*j+1][3]);
            #pragma unroll
            for (int dp = 0; dp < 4; dp++) {
                uint32_t vfr[4];
                uint32_t addr = vb +
                    (uint32_t)((j * 16 + (lid & 15)) * AST + dp * 16 + (lid >> 4) * 8) * 2;
                ldm_x4_t(vfr, addr);
                mma_f16(oacc[dp*2],     pfr, vfr[0], vfr[1]);
                mma_f16(oacc[dp*2 + 1], pfr, vfr[2], vfr[3]);
            }
        }
        __syncthreads();
    }
    #undef KV_ISSUE

    // ---- epilogue: split hi|lo ctx (row stride K2E) ----
    const size_t rowBase = (size_t)(b * SS + q0);
    #pragma unroll
    for (int half = 0; half < 2; half++) {
        float inv = 1.0f / l_run[half];
        size_t m = rowBase + wid * 16 + g + half * 8;
        size_t base = m * K2E + h * DD + tig * 2;
        #pragma unroll
        for (int nt = 0; nt < 8; nt++) {
            float o0 = oacc[nt][half*2]     * inv;
            float o1 = oacc[nt][half*2 + 1] * inv;
            __half h0 = __float2half_rn(o0);
            __half h1 = __float2half_rn(o1);
            __half l0 = __float2half_rn(o0 - __half2float(h0));
            __half l1 = __float2half_rn(o1 - __half2float(h1));
            size_t off = base + nt * 8;
            *(uint32_t*)(Os + off)      = pk2h(h0, h1);
            *(uint32_t*)(Os + off + EE) = pk2h(l0, l1);
        }
    }
}

// ================= split / prep kernels =================
// activation split: x[M,512] fp32 -> xs[M,1024] fp16 as [hi | lo]
__global__ __launch_bounds__(256) void split_act(
    const float* __restrict__ x, __half* __restrict__ xs)
{
    int idx = blockIdx.x * 256 + threadIdx.x;
    int m = idx >> 9, k = idx & 511;
    float v = x[idx];
    __half h = __float2half_rn(v);
    __half l = __float2half_rn(v - __half2float(h));
    size_t base = (size_t)m * K2E;
    xs[base + k] = h; xs[base + EE + k] = l;
}

// weight convert+transpose: W[K,N] fp32 -> Ws[N,2K] fp16 as [Wh | Wh] (dup)
__global__ void conv_wt(const float* __restrict__ W,
                        __half* __restrict__ Ws, int K, int N)
{
    __shared__ float t[32][33];
    int n0 = blockIdx.x * 32, k0 = blockIdx.y * 32;
    for (int i = threadIdx.y; i < 32; i += 8)
        t[i][threadIdx.x] = W[(size_t)(k0 + i) * N + n0 + threadIdx.x];
    __syncthreads();
    for (int i = threadIdx.y; i < 32; i += 8) {
        int n = n0 + i, k = k0 + threadIdx.x;
        __half h = __float2half_rn(t[threadIdx.x][i]);
        size_t base = (size_t)n * 2 * K + k;
        Ws[base] = h; Ws[base + K] = h;
    }
}

// ---------------- layernorm (optional split fp16 out, stride K2E) ----------------
__global__ __launch_bounds__(256) void ln_kernel(
    const float* __restrict__ x, const float* __restrict__ g,
    const float* __restrict__ be, float* __restrict__ y,
    __half* __restrict__ ys)
{
    __shared__ float red[16];
    const int row = blockIdx.x;
    const int tid = threadIdx.x;
    const float* xr = x + (size_t)row * EE;

    float v0 = xr[tid], v1 = xr[tid + 256];
    float s  = v0 + v1;
    float ss = v0*v0 + v1*v1;
    #pragma unroll
    for (int off = 16; off > 0; off >>= 1) {
        s  += __shfl_xor_sync(0xffffffffu, s,  off);
        ss += __shfl_xor_sync(0xffffffffu, ss, off);
    }
    int wid = tid >> 5, lid = tid & 31;
    if (lid == 0) { red[wid] = s; red[wid + 8] = ss; }
    __syncthreads();
    if (tid < 32) {
        float a = (tid < 8)  ? red[tid]     : 0.f;
        float c = (tid < 8)  ? red[tid + 8] : 0.f;
        #pragma unroll
        for (int off = 4; off > 0; off >>= 1) {
            a += __shfl_xor_sync(0xffffffffu, a, off);
            c += __shfl_xor_sync(0xffffffffu, c, off);
        }
        if (tid == 0) { red[0] = a; red[1] = c; }
    }
    __syncthreads();
    float mean = red[0] * (1.0f / EE);
    float var  = fmaxf(red[1] * (1.0f / EE) - mean * mean, 0.f);
    float rstd = rsqrtf(var + LN_EPS);

    float o0 = (v0 - mean) * rstd * g[tid]       + be[tid];
    float o1 = (v1 - mean) * rstd * g[tid + 256] + be[tid + 256];
    float* yr = y + (size_t)row * EE;
    yr[tid] = o0; yr[tid + 256] = o1;

    if (ys) {
        size_t base = (size_t)row * K2E;
        __half h0 = __float2half_rn(o0);
        __half h1 = __float2half_rn(o1);
        __half q0 = __float2half_rn(o0 - __half2float(h0));
        __half q1 = __float2half_rn(o1 - __half2float(h1));
        ys[base + tid]        = h0;  ys[base + tid + 256]        = h1;
        ys[base + EE + tid]   = q0;  ys[base + EE + tid + 256]   = q1;
    }
}

// ---------------- launch ----------------
extern "C" void kernel_launch(void* const* d_in, const int* in_sizes, int n_in,
                              void* d_out, int out_size)
{
    (void)in_sizes; (void)n_in; (void)out_size;
    const float* query = (const float*)d_in[0];
    const float* key_t = (const float*)d_in[1];
    const float* value = (const float*)d_in[2];
    const float* Wq = (const float*)d_in[3];  const float* bq = (const float*)d_in[4];
    const float* Wk = (const float*)d_in[5];  const float* bk = (const float*)d_in[6];
    const float* Wv = (const float*)d_in[7];  const float* bv = (const float*)d_in[8];
    const float* Wo = (const float*)d_in[9];  const float* bo = (const float*)d_in[10];
    const float* g1 = (const float*)d_in[11]; const float* be1 = (const float*)d_in[12];
    const float* g2 = (const float*)d_in[13]; const float* be2 = (const float*)d_in[14];
    const float* W1 = (const float*)d_in[15]; const float* b1 = (const float*)d_in[16];
    const float* W2 = (const float*)d_in[17]; const float* b2 = (const float*)d_in[18];
    float* out = (float*)d_out;

    void *pQ, *pK, *pV, *pTmp, *pX1, *pA, *pB, *pW;
    cudaGetSymbolAddress(&pQ,   g_Qh);
    cudaGetSymbolAddress(&pK,   g_Kh);
    cudaGetSymbolAddress(&pV,   g_Vh);
    cudaGetSymbolAddress(&pTmp, g_tmp);
    cudaGetSymbolAddress(&pX1,  g_x1);
    cudaGetSymbolAddress(&pA,   g_actA);
    cudaGetSymbolAddress(&pB,   g_actB);
    cudaGetSymbolAddress(&pW,   g_ws);
    __half* hQ = (__half*)pQ;
    __half* hK = (__half*)pK;
    __half* hV = (__half*)pV;
    float* fT = (float*)pTmp; float* fX = (float*)pX1;
    __half* actA = (__half*)pA;
    __half* actB = (__half*)pB;
    __half* ws   = (__half*)pW;

    const int ATTN_SMEM = (128 * AST + 4 * 64 * AST) * 2;  // 55296 bytes
    cudaFuncSetAttribute(attn_mma,
                         cudaFuncAttributeMaxDynamicSharedMemorySize, ATTN_SMEM);

    dim3 gE(EE / 128, MM / 128);          // (4, 64)
    dim3 gF(FF / 128, MM / 128);          // (16, 64)
    dim3 wEE(EE / 32, EE / 32), wEF(FF / 32, EE / 32), wFE(EE / 32, FF / 32);
    dim3 wblk(32, 8);
    int splitBlocks = MM * EE / 256;

    // QKV projections -> fp16 outputs
    split_act<<<splitBlocks, 256>>>(query, actA);
    conv_wt<<<wEE, wblk>>>(Wq, ws, EE, EE);
    mma_gemm<3><<<gE, 256>>>(actA, ws, bq, nullptr, nullptr, hQ, EE, K2E);
    split_act<<<splitBlocks, 256>>>(key_t, actA);
    conv_wt<<<wEE, wblk>>>(Wk, ws, EE, EE);
    mma_gemm<3><<<gE, 256>>>(actA, ws, bk, nullptr, nullptr, hK, EE, K2E);
    split_act<<<splitBlocks, 256>>>(value, actA);
    conv_wt<<<wEE, wblk>>>(Wv, ws, EE, EE);
    mma_gemm<3><<<gE, 256>>>(actA, ws, bv, nullptr, nullptr, hV, EE, K2E);

    // HMMA flash attention -> split ctx in actA
    attn_mma<<<dim3(SS / 128, HH, BB), 256, ATTN_SMEM>>>(hQ, hK, hV, actA);

    // O projection + residual(query)
    conv_wt<<<wEE, wblk>>>(Wo, ws, EE, EE);
    mma_gemm<1><<<gE, 256>>>(actA, ws, bo, query, fT, nullptr, EE, K2E);
    // LN1 -> x1 fp32 + split in actA
    ln_kernel<<<MM, 256>>>(fT, g1, be1, fX, actA);
    // FFN1 + exact GELU -> split output in actB
    conv_wt<<<wEF, wblk>>>(W1, ws, EE, FF);
    mma_gemm<2><<<gF, 256>>>(actA, ws, b1, nullptr, nullptr, actB, FF, K2E);
    // FFN2 + residual(x1)
    conv_wt<<<wFE, wblk>>>(W2, ws, FF, EE);
    mma_gemm<1><<<gE, 256>>>(actB, ws, b2, fX, fT, nullptr, EE, K2F);
    // LN2 -> out
    ln_kernel<<<MM, 256>>>(fT, g2, be2, out, nullptr);
}

// round 15
// speedup vs baseline: 2.1203x; 1.4601x over previous
#include <cuda_runtime.h>
#include <cuda_fp16.h>
#include <math.h>
#include <stdint.h>

// Problem dims (fixed)
#define BB 4
#define SS 2048
#define EE 512
#define HH 8
#define DD 64
#define FF 2048
#define MM (BB*SS)          // 8192 tokens
#define LN_EPS 1e-5f

// ---------------- scratch (device globals; no allocation) ----------------
__device__ __half g_Qh[(size_t)MM*EE];
__device__ __half g_Kh[(size_t)MM*EE];
__device__ __half g_Vh[(size_t)MM*EE];
__device__ float g_tmp[MM*EE];
__device__ float g_x1 [MM*EE];
__device__ __half g_actA[(size_t)MM*EE];    // fp16 activations (K=512 stages)
__device__ __half g_actB[(size_t)MM*FF];    // fp16 FFN1 output
__device__ __half g_ws  [(size_t)FF*FF];    // fp16 transposed weights (max 2048x512 / 512x2048)

// ================= helpers =================
__device__ __forceinline__ uint32_t smem_u32(const void* p) {
    uint32_t a;
    asm("{ .reg .u64 t; cvta.to.shared.u64 t, %1; cvt.u32.u64 %0, t; }"
        : "=r"(a) : "l"(p));
    return a;
}
__device__ __forceinline__ void cpasync16(uint32_t s, const void* g) {
    asm volatile("cp.async.cg.shared.global [%0], [%1], 16;" :: "r"(s), "l"(g));
}
__device__ __forceinline__ void cp_commit() {
    asm volatile("cp.async.commit_group;" ::: "memory");
}
__device__ __forceinline__ void ldm_x4(uint32_t* r, uint32_t addr) {
    asm volatile("ldmatrix.sync.aligned.m8n8.x4.shared.b16 {%0,%1,%2,%3}, [%4];"
        : "=r"(r[0]), "=r"(r[1]), "=r"(r[2]), "=r"(r[3]) : "r"(addr));
}
__device__ __forceinline__ void ldm_x4_t(uint32_t* r, uint32_t addr) {
    asm volatile("ldmatrix.sync.aligned.m8n8.x4.trans.shared.b16 {%0,%1,%2,%3}, [%4];"
        : "=r"(r[0]), "=r"(r[1]), "=r"(r[2]), "=r"(r[3]) : "r"(addr));
}
__device__ __forceinline__ void mma_f16(float* c, const uint32_t* a,
                                        uint32_t b0, uint32_t b1) {
    asm volatile(
        "mma.sync.aligned.m16n8k16.row.col.f32.f16.f16.f32 "
        "{%0,%1,%2,%3}, {%4,%5,%6,%7}, {%8,%9}, {%0,%1,%2,%3};"
        : "+f"(c[0]), "+f"(c[1]), "+f"(c[2]), "+f"(c[3])
        : "r"(a[0]), "r"(a[1]), "r"(a[2]), "r"(a[3]), "r"(b0), "r"(b1));
}
__device__ __forceinline__ uint32_t pk2h(__half a, __half b) {
    __half2 t = __halves2half2(a, b);
    return *reinterpret_cast<uint32_t*>(&t);
}
__device__ __forceinline__ uint32_t pk2hf(float a, float b) {
    __half2 t = __floats2half2_rn(a, b);
    return *reinterpret_cast<uint32_t*>(&t);
}

// ================= HMMA (mma.sync) plain fp16 GEMM =================
// C[M,N] = A[M,K] @ B[N,K]^T   (fp16 operands, fp32 accum)
// EPI: 1 = +bias+res fp32 ; 2 = gelu(+bias) -> fp16 ; 3 = +bias -> fp16
// Tile 128x128, BK=32, 8 warps (4m x 2n), 2-stage double buffer (R7 engine).
#define SROW 40

template<int EPI>
__global__ __launch_bounds__(256) void mma_gemm(
    const __half* __restrict__ A, const __half* __restrict__ Bw,
    const float* __restrict__ bias, const float* __restrict__ res,
    float* __restrict__ C, __half* __restrict__ Cs,
    int N, int K2)
{
    __shared__ __half As[2][128 * SROW];
    __shared__ __half Bs[2][128 * SROW];

    const int tid = threadIdx.x;
    const int wid = tid >> 5, lid = tid & 31;
    const int warp_m = wid & 3;
    const int warp_n = wid >> 2;
    const int m0 = blockIdx.y * 128;
    const int n0 = blockIdx.x * 128;

    const uint32_t sA0 = smem_u32(As[0]), sA1 = smem_u32(As[1]);
    const uint32_t sB0 = smem_u32(Bs[0]), sB1 = smem_u32(Bs[1]);

    float acc[2][8][4];
    #pragma unroll
    for (int mt = 0; mt < 2; mt++)
        #pragma unroll
        for (int nt = 0; nt < 8; nt++)
            #pragma unroll
            for (int q = 0; q < 4; q++) acc[mt][nt][q] = 0.f;

    const int nK = K2 / 32;

    const int r0c = tid >> 2, c0c = (tid & 3);
    const int r1c = (tid + 256) >> 2, c1c = ((tid + 256) & 3);
    const uint32_t so0 = (uint32_t)(r0c * SROW + c0c * 8) * 2;
    const uint32_t so1 = (uint32_t)(r1c * SROW + c1c * 8) * 2;

    #define ISSUE(kt, b) do {                                                   \
        const __half* Ag = A + (size_t)m0 * K2 + (size_t)(kt) * 32;             \
        const __half* Bg = Bw + (size_t)n0 * K2 + (size_t)(kt) * 32;            \
        uint32_t _a = (b) ? sA1 : sA0, _b = (b) ? sB1 : sB0;                    \
        cpasync16(_a + so0, Ag + (size_t)r0c * K2 + c0c * 8);                   \
        cpasync16(_a + so1, Ag + (size_t)r1c * K2 + c1c * 8);                   \
        cpasync16(_b + so0, Bg + (size_t)r0c * K2 + c0c * 8);                   \
        cpasync16(_b + so1, Bg + (size_t)r1c * K2 + c1c * 8);                   \
        cp_commit();                                                            \
    } while (0)

    ISSUE(0, 0);

    for (int kt = 0; kt < nK; kt++) {
        const int b = kt & 1;
        if (kt + 1 < nK) {
            ISSUE(kt + 1, b ^ 1);
            asm volatile("cp.async.wait_group 1;" ::: "memory");
        } else {
            asm volatile("cp.async.wait_group 0;" ::: "memory");
        }
        __syncthreads();

        const uint32_t sAb = b ? sA1 : sA0;
        const uint32_t sBb = b ? sB1 : sB0;

        #pragma unroll
        for (int ks = 0; ks < 2; ks++) {
            const int kof = ks * 16;
            uint32_t afr[2][4];
            #pragma unroll
            for (int mt = 0; mt < 2; mt++) {
                uint32_t addr = sAb +
                    (uint32_t)((warp_m * 32 + mt * 16 + (lid & 15)) * SROW
                               + kof + (lid >> 4) * 8) * 2;
                ldm_x4(afr[mt], addr);
            }
            uint32_t bfr[4][4];
            #pragma unroll
            for (int q = 0; q < 4; q++) {
                const int grp = lid >> 3;
                const int n = warp_n * 64 + q * 16 + (grp >> 1) * 8 + (lid & 7);
                uint32_t addr = sBb +
                    (uint32_t)(n * SROW + kof + (grp & 1) * 8) * 2;
                ldm_x4(bfr[q], addr);
            }
            #pragma unroll
            for (int mt = 0; mt < 2; mt++)
                #pragma unroll
                for (int nt = 0; nt < 8; nt++)
                    mma_f16(acc[mt][nt], afr[mt],
                            bfr[nt >> 1][(nt & 1) * 2],
                            bfr[nt >> 1][(nt & 1) * 2 + 1]);
        }
        __syncthreads();
    }
    #undef ISSUE

    // ---- epilogue (direct from fragments) ----
    const int g = lid >> 2, tig = lid & 3;
    const int row_base = m0 + warp_m * 32;
    const int col_base = n0 + warp_n * 64;
    #pragma unroll
    for (int mt = 0; mt < 2; mt++) {
        #pragma unroll
        for (int half = 0; half < 2; half++) {
            const int r = row_base + mt * 16 + g + half * 8;
            #pragma unroll
            for (int nt = 0; nt < 8; nt++) {
                const int cidx = col_base + nt * 8 + tig * 2;
                float v0 = acc[mt][nt][half * 2 + 0] + bias[cidx];
                float v1 = acc[mt][nt][half * 2 + 1] + bias[cidx + 1];
                if (EPI == 1) {
                    const float2 rv = *(const float2*)(res + (size_t)r * N + cidx);
                    v0 += rv.x; v1 += rv.y;
                }
                if (EPI == 2) {
                    v0 = 0.5f * v0 * (1.0f + erff(v0 * 0.70710678118654752f));
                    v1 = 0.5f * v1 * (1.0f + erff(v1 * 0.70710678118654752f));
                    *(uint32_t*)(Cs + (size_t)r * N + cidx) = pk2hf(v0, v1);
                } else if (EPI == 3) {
                    *(uint32_t*)(Cs + (size_t)r * N + cidx) = pk2hf(v0, v1);
                } else {
                    *(float2*)(C + (size_t)r * N + cidx) = make_float2(v0, v1);
                }
            }
        }
    }
}

// ================= HMMA flash attention (fp16) =================
// 128 q-rows / CTA, 8 warps x 16 rows, 64-key blocks, double-buffered K/V.
// Q,K,V fp16 [M,512]; output: plain fp16 ctx [M,512].
#define AST 72   // smem row stride (fp16) = 144B -> ldmatrix conflict-free

__global__ __launch_bounds__(256, 2) void attn_mma(
    const __half* __restrict__ Q, const __half* __restrict__ K,
    const __half* __restrict__ V, __half* __restrict__ Os)
{
    extern __shared__ __half smem[];
    const uint32_t sQ = smem_u32(smem);                       // 128*72
    const uint32_t sK0 = sQ + 128 * AST * 2;                  // 64*72 each
    const uint32_t sV0 = sK0 + 64 * AST * 2;
    const uint32_t sK1 = sV0 + 64 * AST * 2;
    const uint32_t sV1 = sK1 + 64 * AST * 2;

    const int tid = threadIdx.x;
    const int wid = tid >> 5, lid = tid & 31;
    const int g = lid >> 2, tig = lid & 3;
    const int h = blockIdx.y, b = blockIdx.z;
    const int q0 = blockIdx.x * 128;

    const __half* Qg = Q + ((size_t)(b * SS + q0)) * EE + h * DD;
    const __half* Kg = K + ((size_t)(b * SS)) * EE + h * DD;
    const __half* Vg = V + ((size_t)(b * SS)) * EE + h * DD;

    #pragma unroll
    for (int i = 0; i < 4; i++) {
        int idx = tid + i * 256;
        int row = idx >> 3, c8 = (idx & 7) * 8;
        cpasync16(sQ + (uint32_t)(row * AST + c8) * 2, Qg + (size_t)row * EE + c8);
    }

    #define KV_ISSUE(kt, kbuf, vbuf) do {                                   \
        int base_ = (kt) * 64;                                              \
        _Pragma("unroll")                                                   \
        for (int i_ = 0; i_ < 2; i_++) {                                    \
            int idx_ = tid + i_ * 256;                                      \
            int row_ = idx_ >> 3, c8_ = (idx_ & 7) * 8;                     \
            cpasync16((kbuf) + (uint32_t)(row_ * AST + c8_) * 2,            \
                      Kg + (size_t)(base_ + row_) * EE + c8_);              \
            cpasync16((vbuf) + (uint32_t)(row_ * AST + c8_) * 2,            \
                      Vg + (size_t)(base_ + row_) * EE + c8_);              \
        }                                                                   \
        cp_commit();                                                        \
    } while (0)

    KV_ISSUE(0, sK0, sV0);

    float m_run[2] = {-1e30f, -1e30f}, l_run[2] = {0.f, 0.f};
    float oacc[8][4];
    #pragma unroll
    for (int nt = 0; nt < 8; nt++)
        #pragma unroll
        for (int q = 0; q < 4; q++) oacc[nt][q] = 0.f;

    uint32_t qfr[4][4];

    for (int kt = 0; kt < SS / 64; kt++) {
        const int buf = kt & 1;
        const uint32_t kb = buf ? sK1 : sK0;
        const uint32_t vb = buf ? sV1 : sV0;
        if (kt + 1 < SS / 64) {
            const uint32_t nk = buf ? sK0 : sK1;
            const uint32_t nv = buf ? sV0 : sV1;
            KV_ISSUE(kt + 1, nk, nv);
            asm volatile("cp.async.wait_group 1;" ::: "memory");
        } else {
            asm volatile("cp.async.wait_group 0;" ::: "memory");
        }
        __syncthreads();

        if (kt == 0) {
            #pragma unroll
            for (int ks = 0; ks < 4; ks++) {
                uint32_t addr = sQ +
                    (uint32_t)((wid * 16 + (lid & 15)) * AST + ks * 16 + (lid >> 4) * 8) * 2;
                ldm_x4(qfr[ks], addr);
            }
        }

        // ---- S = Q @ K^T ----
        float sfr[8][4];
        #pragma unroll
        for (int nt = 0; nt < 8; nt++)
            #pragma unroll
            for (int q = 0; q < 4; q++) sfr[nt][q] = 0.f;

        const int grp = lid >> 3;
        #pragma unroll
        for (int ks = 0; ks < 4; ks++) {
            uint32_t bfr[4][4];
            #pragma unroll
            for (int q = 0; q < 4; q++) {
                const int n = q * 16 + (grp >> 1) * 8 + (lid & 7);
                uint32_t addr = kb + (uint32_t)(n * AST + ks * 16 + (grp & 1) * 8) * 2;
                ldm_x4(bfr[q], addr);
            }
            #pragma unroll
            for (int nt = 0; nt < 8; nt++)
                mma_f16(sfr[nt], qfr[ks],
                        bfr[nt >> 1][(nt & 1) * 2],
                        bfr[nt >> 1][(nt & 1) * 2 + 1]);
        }

        // ---- online softmax ----
        #pragma unroll
        for (int half = 0; half < 2; half++) {
            float mloc = -1e30f;
            #pragma unroll
            for (int nt = 0; nt < 8; nt++) {
                sfr[nt][half*2]   *= 0.125f;
                sfr[nt][half*2+1] *= 0.125f;
                mloc = fmaxf(mloc, fmaxf(sfr[nt][half*2], sfr[nt][half*2+1]));
            }
            mloc = fmaxf(mloc, __shfl_xor_sync(0xffffffffu, mloc, 1));
            mloc = fmaxf(mloc, __shfl_xor_sync(0xffffffffu, mloc, 2));
            float m_new = fmaxf(m_run[half], mloc);
            float corr = __expf(m_run[half] - m_new);
            m_run[half] = m_new;
            float lsum = 0.f;
            #pragma unroll
            for (int nt = 0; nt < 8; nt++) {
                float p0 = __expf(sfr[nt][half*2]   - m_new);
                float p1 = __expf(sfr[nt][half*2+1] - m_new);
                sfr[nt][half*2] = p0; sfr[nt][half*2+1] = p1;
                lsum += p0 + p1;
            }
            lsum += __shfl_xor_sync(0xffffffffu, lsum, 1);
            lsum += __shfl_xor_sync(0xffffffffu, lsum, 2);
            l_run[half] = l_run[half] * corr + lsum;
            #pragma unroll
            for (int nt = 0; nt < 8; nt++) {
                oacc[nt][half*2]   *= corr;
                oacc[nt][half*2+1] *= corr;
            }
        }

        // ---- O += P @ V ----
        #pragma unroll
        for (int j = 0; j < 4; j++) {
            uint32_t pfr[4];
            pfr[0] = pk2hf(sfr[2*j][0],   sfr[2*j][1]);
            pfr[1] = pk2hf(sfr[2*j][2],   sfr[2*j][3]);
            pfr[2] = pk2hf(sfr[2*j+1][0], sfr[2*j+1][1]);
            pfr[3] = pk2hf(sfr[2*j+1][2], sfr[2*j+1][3]);
            #pragma unroll
            for (int dp = 0; dp < 4; dp++) {
                uint32_t vfr[4];
                uint32_t addr = vb +
                    (uint32_t)((j * 16 + (lid & 15)) * AST + dp * 16 + (lid >> 4) * 8) * 2;
                ldm_x4_t(vfr, addr);
                mma_f16(oacc[dp*2],     pfr, vfr[0], vfr[1]);
                mma_f16(oacc[dp*2 + 1], pfr, vfr[2], vfr[3]);
            }
        }
        __syncthreads();
    }
    #undef KV_ISSUE

    // ---- epilogue: plain fp16 ctx [M, EE] ----
    const size_t rowBase = (size_t)(b * SS + q0);
    #pragma unroll
    for (int half = 0; half < 2; half++) {
        float inv = 1.0f / l_run[half];
        size_t m = rowBase + wid * 16 + g + half * 8;
        size_t base = m * EE + h * DD + tig * 2;
        #pragma unroll
        for (int nt = 0; nt < 8; nt++) {
            float o0 = oacc[nt][half*2]     * inv;
            float o1 = oacc[nt][half*2 + 1] * inv;
            *(uint32_t*)(Os + base + nt * 8) = pk2hf(o0, o1);
        }
    }
}

// ================= prep kernels =================
// activation convert: x[M,512] fp32 -> xs[M,512] fp16
__global__ __launch_bounds__(256) void conv_act(
    const float* __restrict__ x, __half* __restrict__ xs)
{
    int idx = blockIdx.x * 256 + threadIdx.x;
    float2 v = *(const float2*)(x + (size_t)idx * 2);
    *(uint32_t*)(xs + (size_t)idx * 2) = pk2hf(v.x, v.y);
}

// weight convert+transpose: W[K,N] fp32 -> Ws[N,K] fp16
__global__ void conv_wt(const float* __restrict__ W,
                        __half* __restrict__ Ws, int K, int N)
{
    __shared__ float t[32][33];
    int n0 = blockIdx.x * 32, k0 = blockIdx.y * 32;
    for (int i = threadIdx.y; i < 32; i += 8)
        t[i][threadIdx.x] = W[(size_t)(k0 + i) * N + n0 + threadIdx.x];
    __syncthreads();
    for (int i = threadIdx.y; i < 32; i += 8) {
        int n = n0 + i, k = k0 + threadIdx.x;
        Ws[(size_t)n * K + k] = __float2half_rn(t[threadIdx.x][i]);
    }
}

// ---------------- layernorm (optional fp16 out) ----------------
__global__ __launch_bounds__(256) void ln_kernel(
    const float* __restrict__ x, const float* __restrict__ g,
    const float* __restrict__ be, float* __restrict__ y,
    __half* __restrict__ ys)
{
    __shared__ float red[16];
    const int row = blockIdx.x;
    const int tid = threadIdx.x;
    const float* xr = x + (size_t)row * EE;

    float v0 = xr[tid], v1 = xr[tid + 256];
    float s  = v0 + v1;
    float ss = v0*v0 + v1*v1;
    #pragma unroll
    for (int off = 16; off > 0; off >>= 1) {
        s  += __shfl_xor_sync(0xffffffffu, s,  off);
        ss += __shfl_xor_sync(0xffffffffu, ss, off);
    }
    int wid = tid >> 5, lid = tid & 31;
    if (lid == 0) { red[wid] = s; red[wid + 8] = ss; }
    __syncthreads();
    if (tid < 32) {
        float a = (tid < 8)  ? red[tid]     : 0.f;
        float c = (tid < 8)  ? red[tid + 8] : 0.f;
        #pragma unroll
        for (int off = 4; off > 0; off >>= 1) {
            a += __shfl_xor_sync(0xffffffffu, a, off);
            c += __shfl_xor_sync(0xffffffffu, c, off);
        }
        if (tid == 0) { red[0] = a; red[1] = c; }
    }
    __syncthreads();
    float mean = red[0] * (1.0f / EE);
    float var  = fmaxf(red[1] * (1.0f / EE) - mean * mean, 0.f);
    float rstd = rsqrtf(var + LN_EPS);

    float o0 = (v0 - mean) * rstd * g[tid]       + be[tid];
    float o1 = (v1 - mean) * rstd * g[tid + 256] + be[tid + 256];
    float* yr = y + (size_t)row * EE;
    yr[tid] = o0; yr[tid + 256] = o1;

    if (ys) {
        size_t base = (size_t)row * EE;
        ys[base + tid]       = __float2half_rn(o0);
        ys[base + tid + 256] = __float2half_rn(o1);
    }
}

// ---------------- launch ----------------
extern "C" void kernel_launch(void* const* d_in, const int* in_sizes, int n_in,
                              void* d_out, int out_size)
{
    (void)in_sizes; (void)n_in; (void)out_size;
    const float* query = (const float*)d_in[0];
    const float* key_t = (const float*)d_in[1];
    const float* value = (const float*)d_in[2];
    const float* Wq = (const float*)d_in[3];  const float* bq = (const float*)d_in[4];
    const float* Wk = (const float*)d_in[5];  const float* bk = (const float*)d_in[6];
    const float* Wv = (const float*)d_in[7];  const float* bv = (const float*)d_in[8];
    const float* Wo = (const float*)d_in[9];  const float* bo = (const float*)d_in[10];
    const float* g1 = (const float*)d_in[11]; const float* be1 = (const float*)d_in[12];
    const float* g2 = (const float*)d_in[13]; const float* be2 = (const float*)d_in[14];
    const float* W1 = (const float*)d_in[15]; const float* b1 = (const float*)d_in[16];
    const float* W2 = (const float*)d_in[17]; const float* b2 = (const float*)d_in[18];
    float* out = (float*)d_out;

    void *pQ, *pK, *pV, *pTmp, *pX1, *pA, *pB, *pW;
    cudaGetSymbolAddress(&pQ,   g_Qh);
    cudaGetSymbolAddress(&pK,   g_Kh);
    cudaGetSymbolAddress(&pV,   g_Vh);
    cudaGetSymbolAddress(&pTmp, g_tmp);
    cudaGetSymbolAddress(&pX1,  g_x1);
    cudaGetSymbolAddress(&pA,   g_actA);
    cudaGetSymbolAddress(&pB,   g_actB);
    cudaGetSymbolAddress(&pW,   g_ws);
    __half* hQ = (__half*)pQ;
    __half* hK = (__half*)pK;
    __half* hV = (__half*)pV;
    float* fT = (float*)pTmp; float* fX = (float*)pX1;
    __half* actA = (__half*)pA;
    __half* actB = (__half*)pB;
    __half* ws   = (__half*)pW;

    const int ATTN_SMEM = (128 * AST + 4 * 64 * AST) * 2;  // 55296 bytes
    cudaFuncSetAttribute(attn_mma,
                         cudaFuncAttributeMaxDynamicSharedMemorySize, ATTN_SMEM);

    dim3 gE(EE / 128, MM / 128);          // (4, 64)
    dim3 gF(FF / 128, MM / 128);          // (16, 64)
    dim3 wEE(EE / 32, EE / 32), wEF(FF / 32, EE / 32), wFE(EE / 32, FF / 32);
    dim3 wblk(32, 8);
    int convBlocks = MM * EE / 512;       // conv_act: 2 elems/thread

    // QKV projections -> fp16 outputs
    conv_act<<<convBlocks, 256>>>(query, actA);
    conv_wt<<<wEE, wblk>>>(Wq, ws, EE, EE);
    mma_gemm<3><<<gE, 256>>>(actA, ws, bq, nullptr, nullptr, hQ, EE, EE);
    conv_act<<<convBlocks, 256>>>(key_t, actA);
    conv_wt<<<wEE, wblk>>>(Wk, ws, EE, EE);
    mma_gemm<3><<<gE, 256>>>(actA, ws, bk, nullptr, nullptr, hK, EE, EE);
    conv_act<<<convBlocks, 256>>>(value, actA);
    conv_wt<<<wEE, wblk>>>(Wv, ws, EE, EE);
    mma_gemm<3><<<gE, 256>>>(actA, ws, bv, nullptr, nullptr, hV, EE, EE);

    // HMMA flash attention -> fp16 ctx in actA
    attn_mma<<<dim3(SS / 128, HH, BB), 256, ATTN_SMEM>>>(hQ, hK, hV, actA);

    // O projection + residual(query)
    conv_wt<<<wEE, wblk>>>(Wo, ws, EE, EE);
    mma_gemm<1><<<gE, 256>>>(actA, ws, bo, query, fT, nullptr, EE, EE);
    // LN1 -> x1 fp32 + fp16 in actA
    ln_kernel<<<MM, 256>>>(fT, g1, be1, fX, actA);
    // FFN1 + exact GELU -> fp16 in actB
    conv_wt<<<wEF, wblk>>>(W1, ws, EE, FF);
    mma_gemm<2><<<gF, 256>>>(actA, ws, b1, nullptr, nullptr, actB, FF, EE);
    // FFN2 + residual(x1)
    conv_wt<<<wFE, wblk>>>(W2, ws, FF, EE);
    mma_gemm<1><<<gE, 256>>>(actB, ws, b2, fX, fT, nullptr, EE, FF);
    // LN2 -> out
    ln_kernel<<<MM, 256>>>(fT, g2, be2, out, nullptr);
}

// round 16
// speedup vs baseline: 2.1910x; 1.0333x over previous
#include <cuda_runtime.h>
#include <cuda_fp16.h>
#include <math.h>
#include <stdint.h>

// Problem dims (fixed)
#define BB 4
#define SS 2048
#define EE 512
#define HH 8
#define DD 64
#define FF 2048
#define MM (BB*SS)          // 8192 tokens
#define LN_EPS 1e-5f

// weight offsets in g_ws (fp16 elems)
#define WOFF_Q  0u
#define WOFF_K  262144u
#define WOFF_V  524288u
#define WOFF_O  786432u
#define WOFF_1  1048576u
#define WOFF_2  2097152u

// ---------------- scratch (device globals; no allocation) ----------------
__device__ __half g_Qh[(size_t)MM*EE];
__device__ __half g_Kh[(size_t)MM*EE];
__device__ __half g_Vh[(size_t)MM*EE];
__device__ float g_tmp[MM*EE];
__device__ float g_x1 [MM*EE];
__device__ __half g_actA[(size_t)MM*EE];    // query act -> ctx -> LN1 act
__device__ __half g_actB[(size_t)MM*FF];    // key act | value act -> FFN1 output
__device__ __half g_ws  [(size_t)4*1024*1024]; // all 6 converted weights (3.07M used)

// ================= helpers =================
__device__ __forceinline__ uint32_t smem_u32(const void* p) {
    uint32_t a;
    asm("{ .reg .u64 t; cvta.to.shared.u64 t, %1; cvt.u32.u64 %0, t; }"
        : "=r"(a) : "l"(p));
    return a;
}
__device__ __forceinline__ void cpasync16(uint32_t s, const void* g) {
    asm volatile("cp.async.cg.shared.global [%0], [%1], 16;" :: "r"(s), "l"(g));
}
__device__ __forceinline__ void cp_commit() {
    asm volatile("cp.async.commit_group;" ::: "memory");
}
__device__ __forceinline__ void ldm_x4(uint32_t* r, uint32_t addr) {
    asm volatile("ldmatrix.sync.aligned.m8n8.x4.shared.b16 {%0,%1,%2,%3}, [%4];"
        : "=r"(r[0]), "=r"(r[1]), "=r"(r[2]), "=r"(r[3]) : "r"(addr));
}
__device__ __forceinline__ void ldm_x4_t(uint32_t* r, uint32_t addr) {
    asm volatile("ldmatrix.sync.aligned.m8n8.x4.trans.shared.b16 {%0,%1,%2,%3}, [%4];"
        : "=r"(r[0]), "=r"(r[1]), "=r"(r[2]), "=r"(r[3]) : "r"(addr));
}
__device__ __forceinline__ void mma_f16(float* c, const uint32_t* a,
                                        uint32_t b0, uint32_t b1) {
    asm volatile(
        "mma.sync.aligned.m16n8k16.row.col.f32.f16.f16.f32 "
        "{%0,%1,%2,%3}, {%4,%5,%6,%7}, {%8,%9}, {%0,%1,%2,%3};"
        : "+f"(c[0]), "+f"(c[1]), "+f"(c[2]), "+f"(c[3])
        : "r"(a[0]), "r"(a[1]), "r"(a[2]), "r"(a[3]), "r"(b0), "r"(b1));
}
__device__ __forceinline__ uint32_t pk2hf(float a, float b) {
    __half2 t = __floats2half2_rn(a, b);
    return *reinterpret_cast<uint32_t*>(&t);
}

// ================= GEMM core (shared by both GEMM kernels) =================
// Tile 128x128, BK=32, 8 warps (4m x 2n), 2-stage double buffer.
#define SROW 40

#define GEMM_CORE(Aptr, Bptr, K2)                                               \
    __shared__ __half As[2][128 * SROW];                                        \
    __shared__ __half Bs[2][128 * SROW];                                        \
    const int tid = threadIdx.x;                                                \
    const int wid = tid >> 5, lid = tid & 31;                                   \
    const int warp_m = wid & 3;                                                 \
    const int warp_n = wid >> 2;                                                \
    const int m0 = blockIdx.y * 128;                                            \
    const int n0 = blockIdx.x * 128;                                            \
    const uint32_t sA0 = smem_u32(As[0]), sA1 = smem_u32(As[1]);                \
    const uint32_t sB0 = smem_u32(Bs[0]), sB1 = smem_u32(Bs[1]);                \
    float acc[2][8][4];                                                         \
    _Pragma("unroll")                                                           \
    for (int mt = 0; mt < 2; mt++)                                              \
        _Pragma("unroll")                                                       \
        for (int nt = 0; nt < 8; nt++)                                          \
            _Pragma("unroll")                                                   \
            for (int q = 0; q < 4; q++) acc[mt][nt][q] = 0.f;                   \
    const int nK = (K2) / 32;                                                   \
    const int r0c = tid >> 2, c0c = (tid & 3);                                  \
    const int r1c = (tid + 256) >> 2, c1c = ((tid + 256) & 3);                  \
    const uint32_t so0 = (uint32_t)(r0c * SROW + c0c * 8) * 2;                  \
    const uint32_t so1 = (uint32_t)(r1c * SROW + c1c * 8) * 2;                  \
    ISSUE(Aptr, Bptr, K2, 0, 0);                                                \
    for (int kt = 0; kt < nK; kt++) {                                           \
        const int b = kt & 1;                                                   \
        if (kt + 1 < nK) {                                                      \
            ISSUE(Aptr, Bptr, K2, kt + 1, b ^ 1);                               \
            asm volatile("cp.async.wait_group 1;" ::: "memory");                \
        } else {                                                                \
            asm volatile("cp.async.wait_group 0;" ::: "memory");                \
        }                                                                       \
        __syncthreads();                                                        \
        const uint32_t sAb = b ? sA1 : sA0;                                     \
        const uint32_t sBb = b ? sB1 : sB0;                                     \
        _Pragma("unroll")                                                       \
        for (int ks = 0; ks < 2; ks++) {                                        \
            const int kof = ks * 16;                                            \
            uint32_t afr[2][4];                                                 \
            _Pragma("unroll")                                                   \
            for (int mt = 0; mt < 2; mt++) {                                    \
                uint32_t addr = sAb +                                           \
                    (uint32_t)((warp_m * 32 + mt * 16 + (lid & 15)) * SROW      \
                               + kof + (lid >> 4) * 8) * 2;                     \
                ldm_x4(afr[mt], addr);                                          \
            }                                                                   \
            uint32_t bfr[4][4];                                                 \
            _Pragma("unroll")                                                   \
            for (int q = 0; q < 4; q++) {                                       \
                const int grp = lid >> 3;                                       \
                const int n = warp_n * 64 + q * 16 + (grp >> 1) * 8 + (lid & 7);\
                uint32_t addr = sBb +                                           \
                    (uint32_t)(n * SROW + kof + (grp & 1) * 8) * 2;             \
                ldm_x4(bfr[q], addr);                                           \
            }                                                                   \
            _Pragma("unroll")                                                   \
            for (int mt = 0; mt < 2; mt++)                                      \
                _Pragma("unroll")                                               \
                for (int nt = 0; nt < 8; nt++)                                  \
                    mma_f16(acc[mt][nt], afr[mt],                               \
                            bfr[nt >> 1][(nt & 1) * 2],                         \
                            bfr[nt >> 1][(nt & 1) * 2 + 1]);                    \
        }                                                                       \
        __syncthreads();                                                        \
    }

#define ISSUE(Aptr, Bptr, K2, kt, b) do {                                       \
        const __half* Ag = (Aptr) + (size_t)m0 * (K2) + (size_t)(kt) * 32;      \
        const __half* Bg = (Bptr) + (size_t)n0 * (K2) + (size_t)(kt) * 32;      \
        uint32_t _a = (b) ? sA1 : sA0, _b = (b) ? sB1 : sB0;                    \
        cpasync16(_a + so0, Ag + (size_t)r0c * (K2) + c0c * 8);                 \
        cpasync16(_a + so1, Ag + (size_t)r1c * (K2) + c1c * 8);                 \
        cpasync16(_b + so0, Bg + (size_t)r0c * (K2) + c0c * 8);                 \
        cpasync16(_b + so1, Bg + (size_t)r1c * (K2) + c1c * 8);                 \
        cp_commit();                                                            \
    } while (0)

// ---- general GEMM: EPI 1 = +bias+res fp32 ; 2 = gelu(+bias) -> fp16 ----
template<int EPI>
__global__ __launch_bounds__(256) void mma_gemm(
    const __half* __restrict__ A, const __half* __restrict__ Bw,
    const float* __restrict__ bias, const float* __restrict__ res,
    float* __restrict__ C, __half* __restrict__ Cs,
    int N, int K2)
{
    GEMM_CORE(A, Bw, K2)

    const int g = lid >> 2, tig = lid & 3;
    const int row_base = m0 + warp_m * 32;
    const int col_base = n0 + warp_n * 64;
    #pragma unroll
    for (int mt = 0; mt < 2; mt++) {
        #pragma unroll
        for (int half = 0; half < 2; half++) {
            const int r = row_base + mt * 16 + g + half * 8;
            #pragma unroll
            for (int nt = 0; nt < 8; nt++) {
                const int cidx = col_base + nt * 8 + tig * 2;
                float v0 = acc[mt][nt][half * 2 + 0] + bias[cidx];
                float v1 = acc[mt][nt][half * 2 + 1] + bias[cidx + 1];
                if (EPI == 1) {
                    const float2 rv = *(const float2*)(res + (size_t)r * N + cidx);
                    v0 += rv.x; v1 += rv.y;
                    *(float2*)(C + (size_t)r * N + cidx) = make_float2(v0, v1);
                }
                if (EPI == 2) {
                    v0 = 0.5f * v0 * (1.0f + erff(v0 * 0.70710678118654752f));
                    v1 = 0.5f * v1 * (1.0f + erff(v1 * 0.70710678118654752f));
                    *(uint32_t*)(Cs + (size_t)r * N + cidx) = pk2hf(v0, v1);
                }
            }
        }
    }
}

// ---- 3-in-1 projection GEMM: z selects (A, W, bias, out); +bias -> fp16 ----
struct Proj3 {
    const __half* A[3];
    const __half* Bw[3];
    const float*  bias[3];
    __half*       out[3];
};

__global__ __launch_bounds__(256) void mma_gemm_proj(Proj3 p)
{
    const __half* Ap  = p.A[blockIdx.z];
    const __half* Bwp = p.Bw[blockIdx.z];
    const float*  bp  = p.bias[blockIdx.z];
    __half*       op  = p.out[blockIdx.z];

    GEMM_CORE(Ap, Bwp, EE)

    const int g = lid >> 2, tig = lid & 3;
    const int row_base = m0 + warp_m * 32;
    const int col_base = n0 + warp_n * 64;
    #pragma unroll
    for (int mt = 0; mt < 2; mt++) {
        #pragma unroll
        for (int half = 0; half < 2; half++) {
            const int r = row_base + mt * 16 + g + half * 8;
            #pragma unroll
            for (int nt = 0; nt < 8; nt++) {
                const int cidx = col_base + nt * 8 + tig * 2;
                float v0 = acc[mt][nt][half * 2 + 0] + bp[cidx];
                float v1 = acc[mt][nt][half * 2 + 1] + bp[cidx + 1];
                *(uint32_t*)(op + (size_t)r * EE + cidx) = pk2hf(v0, v1);
            }
        }
    }
}

// ================= HMMA flash attention (fp16) =================
#define AST 72   // smem row stride (fp16) = 144B -> ldmatrix conflict-free

__global__ __launch_bounds__(256, 2) void attn_mma(
    const __half* __restrict__ Q, const __half* __restrict__ K,
    const __half* __restrict__ V, __half* __restrict__ Os)
{
    extern __shared__ __half smem[];
    const uint32_t sQ = smem_u32(smem);
    const uint32_t sK0 = sQ + 128 * AST * 2;
    const uint32_t sV0 = sK0 + 64 * AST * 2;
    const uint32_t sK1 = sV0 + 64 * AST * 2;
    const uint32_t sV1 = sK1 + 64 * AST * 2;

    const int tid = threadIdx.x;
    const int wid = tid >> 5, lid = tid & 31;
    const int g = lid >> 2, tig = lid & 3;
    const int h = blockIdx.y, b = blockIdx.z;
    const int q0 = blockIdx.x * 128;

    const __half* Qg = Q + ((size_t)(b * SS + q0)) * EE + h * DD;
    const __half* Kg = K + ((size_t)(b * SS)) * EE + h * DD;
    const __half* Vg = V + ((size_t)(b * SS)) * EE + h * DD;

    #pragma unroll
    for (int i = 0; i < 4; i++) {
        int idx = tid + i * 256;
        int row = idx >> 3, c8 = (idx & 7) * 8;
        cpasync16(sQ + (uint32_t)(row * AST + c8) * 2, Qg + (size_t)row * EE + c8);
    }

    #define KV_ISSUE(kt, kbuf, vbuf) do {                                   \
        int base_ = (kt) * 64;                                              \
        _Pragma("unroll")                                                   \
        for (int i_ = 0; i_ < 2; i_++) {                                    \
            int idx_ = tid + i_ * 256;                                      \
            int row_ = idx_ >> 3, c8_ = (idx_ & 7) * 8;                     \
            cpasync16((kbuf) + (uint32_t)(row_ * AST + c8_) * 2,            \
                      Kg + (size_t)(base_ + row_) * EE + c8_);              \
            cpasync16((vbuf) + (uint32_t)(row_ * AST + c8_) * 2,            \
                      Vg + (size_t)(base_ + row_) * EE + c8_);              \
        }                                                                   \
        cp_commit();                                                        \
    } while (0)

    KV_ISSUE(0, sK0, sV0);

    float m_run[2] = {-1e30f, -1e30f}, l_run[2] = {0.f, 0.f};
    float oacc[8][4];
    #pragma unroll
    for (int nt = 0; nt < 8; nt++)
        #pragma unroll
        for (int q = 0; q < 4; q++) oacc[nt][q] = 0.f;

    uint32_t qfr[4][4];

    for (int kt = 0; kt < SS / 64; kt++) {
        const int buf = kt & 1;
        const uint32_t kb = buf ? sK1 : sK0;
        const uint32_t vb = buf ? sV1 : sV0;
        if (kt + 1 < SS / 64) {
            const uint32_t nk = buf ? sK0 : sK1;
            const uint32_t nv = buf ? sV0 : sV1;
            KV_ISSUE(kt + 1, nk, nv);
            asm volatile("cp.async.wait_group 1;" ::: "memory");
        } else {
            asm volatile("cp.async.wait_group 0;" ::: "memory");
        }
        __syncthreads();

        if (kt == 0) {
            #pragma unroll
            for (int ks = 0; ks < 4; ks++) {
                uint32_t addr = sQ +
                    (uint32_t)((wid * 16 + (lid & 15)) * AST + ks * 16 + (lid >> 4) * 8) * 2;
                ldm_x4(qfr[ks], addr);
            }
        }

        // ---- S = Q @ K^T ----
        float sfr[8][4];
        #pragma unroll
        for (int nt = 0; nt < 8; nt++)
            #pragma unroll
            for (int q = 0; q < 4; q++) sfr[nt][q] = 0.f;

        const int grp = lid >> 3;
        #pragma unroll
        for (int ks = 0; ks < 4; ks++) {
            uint32_t bfr[4][4];
            #pragma unroll
            for (int q = 0; q < 4; q++) {
                const int n = q * 16 + (grp >> 1) * 8 + (lid & 7);
                uint32_t addr = kb + (uint32_t)(n * AST + ks * 16 + (grp & 1) * 8) * 2;
                ldm_x4(bfr[q], addr);
            }
            #pragma unroll
            for (int nt = 0; nt < 8; nt++)
                mma_f16(sfr[nt], qfr[ks],
                        bfr[nt >> 1][(nt & 1) * 2],
                        bfr[nt >> 1][(nt & 1) * 2 + 1]);
        }

        // ---- online softmax ----
        #pragma unroll
        for (int half = 0; half < 2; half++) {
            float mloc = -1e30f;
            #pragma unroll
            for (int nt = 0; nt < 8; nt++) {
                sfr[nt][half*2]   *= 0.125f;
                sfr[nt][half*2+1] *= 0.125f;
                mloc = fmaxf(mloc, fmaxf(sfr[nt][half*2], sfr[nt][half*2+1]));
            }
            mloc = fmaxf(mloc, __shfl_xor_sync(0xffffffffu, mloc, 1));
            mloc = fmaxf(mloc, __shfl_xor_sync(0xffffffffu, mloc, 2));
            float m_new = fmaxf(m_run[half], mloc);
            float corr = __expf(m_run[half] - m_new);
            m_run[half] = m_new;
            float lsum = 0.f;
            #pragma unroll
            for (int nt = 0; nt < 8; nt++) {
                float p0 = __expf(sfr[nt][half*2]   - m_new);
                float p1 = __expf(sfr[nt][half*2+1] - m_new);
                sfr[nt][half*2] = p0; sfr[nt][half*2+1] = p1;
                lsum += p0 + p1;
            }
            lsum += __shfl_xor_sync(0xffffffffu, lsum, 1);
            lsum += __shfl_xor_sync(0xffffffffu, lsum, 2);
            l_run[half] = l_run[half] * corr + lsum;
            #pragma unroll
            for (int nt = 0; nt < 8; nt++) {
                oacc[nt][half*2]   *= corr;
                oacc[nt][half*2+1] *= corr;
            }
        }

        // ---- O += P @ V ----
        #pragma unroll
        for (int j = 0; j < 4; j++) {
            uint32_t pfr[4];
            pfr[0] = pk2hf(sfr[2*j][0],   sfr[2*j][1]);
            pfr[1] = pk2hf(sfr[2*j][2],   sfr[2*j][3]);
            pfr[2] = pk2hf(sfr[2*j+1][0], sfr[2*j+1][1]);
            pfr[3] = pk2hf(sfr[2*j+1][2], sfr[2*j+1][3]);
            #pragma unroll
            for (int dp = 0; dp < 4; dp++) {
                uint32_t vfr[4];
                uint32_t addr = vb +
                    (uint32_t)((j * 16 + (lid & 15)) * AST + dp * 16 + (lid >> 4) * 8) * 2;
                ldm_x4_t(vfr, addr);
                mma_f16(oacc[dp*2],     pfr, vfr[0], vfr[1]);
                mma_f16(oacc[dp*2 + 1], pfr, vfr[2], vfr[3]);
            }
        }
        __syncthreads();
    }
    #undef KV_ISSUE

    // ---- epilogue: plain fp16 ctx [M, EE] ----
    const size_t rowBase = (size_t)(b * SS + q0);
    #pragma unroll
    for (int half = 0; half < 2; half++) {
        float inv = 1.0f / l_run[half];
        size_t m = rowBase + wid * 16 + g + half * 8;
        size_t base = m * EE + h * DD + tig * 2;
        #pragma unroll
        for (int nt = 0; nt < 8; nt++) {
            float o0 = oacc[nt][half*2]     * inv;
            float o1 = oacc[nt][half*2 + 1] * inv;
            *(uint32_t*)(Os + base + nt * 8) = pk2hf(o0, o1);
        }
    }
}

// ================= fused prep kernels =================
// all three activation conversions in one launch
__global__ __launch_bounds__(256) void prep_act(
    const float* __restrict__ q, const float* __restrict__ k,
    const float* __restrict__ v,
    __half* __restrict__ aq, __half* __restrict__ ak, __half* __restrict__ av)
{
    const size_t per = (size_t)MM * EE / 2;
    size_t idx = (size_t)blockIdx.x * 256 + threadIdx.x;
    const float* src; __half* dst; size_t o;
    if (idx < per)            { src = q; dst = aq; o = idx; }
    else if (idx < 2 * per)   { src = k; dst = ak; o = idx - per; }
    else                      { src = v; dst = av; o = idx - 2 * per; }
    float2 x = ((const float2*)src)[o];
    ((uint32_t*)dst)[o] = pk2hf(x.x, x.y);
}

// all six weight transposes/conversions in one launch (3072 tiles of 32x32)
__global__ void prep_wt(
    const float* __restrict__ Wq, const float* __restrict__ Wk,
    const float* __restrict__ Wv, const float* __restrict__ Wo,
    const float* __restrict__ W1, const float* __restrict__ W2,
    __half* __restrict__ ws)
{
    __shared__ float t[32][33];
    const int tI = blockIdx.x;
    const float* W; __half* Ws; int K, N, n0, k0;
    if (tI < 1024) {
        int w = tI >> 8, tt = tI & 255;
        W  = (w == 0) ? Wq : (w == 1) ? Wk : (w == 2) ? Wv : Wo;
        Ws = ws + (size_t)w * 262144u;
        K = 512; N = 512;
        n0 = (tt & 15) * 32; k0 = (tt >> 4) * 32;
    } else if (tI < 2048) {
        int tt = tI - 1024;
        W = W1; Ws = ws + WOFF_1;
        K = 512; N = 2048;
        n0 = (tt & 63) * 32; k0 = (tt >> 6) * 32;
    } else {
        int tt = tI - 2048;
        W = W2; Ws = ws + WOFF_2;
        K = 2048; N = 512;
        n0 = (tt & 15) * 32; k0 = (tt >> 4) * 32;
    }
    for (int i = threadIdx.y; i < 32; i += 8)
        t[i][threadIdx.x] = W[(size_t)(k0 + i) * N + n0 + threadIdx.x];
    __syncthreads();
    for (int i = threadIdx.y; i < 32; i += 8) {
        int n = n0 + i, k = k0 + threadIdx.x;
        Ws[(size_t)n * K + k] = __float2half_rn(t[threadIdx.x][i]);
    }
}

// ---------------- layernorm (optional fp16 out) ----------------
__global__ __launch_bounds__(256) void ln_kernel(
    const float* __restrict__ x, const float* __restrict__ g,
    const float* __restrict__ be, float* __restrict__ y,
    __half* __restrict__ ys)
{
    __shared__ float red[16];
    const int row = blockIdx.x;
    const int tid = threadIdx.x;
    const float* xr = x + (size_t)row * EE;

    float v0 = xr[tid], v1 = xr[tid + 256];
    float s  = v0 + v1;
    float ss = v0*v0 + v1*v1;
    #pragma unroll
    for (int off = 16; off > 0; off >>= 1) {
        s  += __shfl_xor_sync(0xffffffffu, s,  off);
        ss += __shfl_xor_sync(0xffffffffu, ss, off);
    }
    int wid = tid >> 5, lid = tid & 31;
    if (lid == 0) { red[wid] = s; red[wid + 8] = ss; }
    __syncthreads();
    if (tid < 32) {
        float a = (tid < 8)  ? red[tid]     : 0.f;
        float c = (tid < 8)  ? red[tid + 8] : 0.f;
        #pragma unroll
        for (int off = 4; off > 0; off >>= 1) {
            a += __shfl_xor_sync(0xffffffffu, a, off);
            c += __shfl_xor_sync(0xffffffffu, c, off);
        }
        if (tid == 0) { red[0] = a; red[1] = c; }
    }
    __syncthreads();
    float mean = red[0] * (1.0f / EE);
    float var  = fmaxf(red[1] * (1.0f / EE) - mean * mean, 0.f);
    float rstd = rsqrtf(var + LN_EPS);

    float o0 = (v0 - mean) * rstd * g[tid]       + be[tid];
    float o1 = (v1 - mean) * rstd * g[tid + 256] + be[tid + 256];
    float* yr = y + (size_t)row * EE;
    yr[tid] = o0; yr[tid + 256] = o1;

    if (ys) {
        size_t base = (size_t)row * EE;
        ys[base + tid]       = __float2half_rn(o0);
        ys[base + tid + 256] = __float2half_rn(o1);
    }
}

// ---------------- launch ----------------
extern "C" void kernel_launch(void* const* d_in, const int* in_sizes, int n_in,
                              void* d_out, int out_size)
{
    (void)in_sizes; (void)n_in; (void)out_size;
    const float* query = (const float*)d_in[0];
    const float* key_t = (const float*)d_in[1];
    const float* value = (const float*)d_in[2];
    const float* Wq = (const float*)d_in[3];  const float* bq = (const float*)d_in[4];
    const float* Wk = (const float*)d_in[5];  const float* bk = (const float*)d_in[6];
    const float* Wv = (const float*)d_in[7];  const float* bv = (const float*)d_in[8];
    const float* Wo = (const float*)d_in[9];  const float* bo = (const float*)d_in[10];
    const float* g1 = (const float*)d_in[11]; const float* be1 = (const float*)d_in[12];
    const float* g2 = (const float*)d_in[13]; const float* be2 = (const float*)d_in[14];
    const float* W1 = (const float*)d_in[15]; const float* b1 = (const float*)d_in[16];
    const float* W2 = (const float*)d_in[17]; const float* b2 = (const float*)d_in[18];
    float* out = (float*)d_out;

    void *pQ, *pK, *pV, *pTmp, *pX1, *pA, *pB, *pW;
    cudaGetSymbolAddress(&pQ,   g_Qh);
    cudaGetSymbolAddress(&pK,   g_Kh);
    cudaGetSymbolAddress(&pV,   g_Vh);
    cudaGetSymbolAddress(&pTmp, g_tmp);
    cudaGetSymbolAddress(&pX1,  g_x1);
    cudaGetSymbolAddress(&pA,   g_actA);
    cudaGetSymbolAddress(&pB,   g_actB);
    cudaGetSymbolAddress(&pW,   g_ws);
    __half* hQ = (__half*)pQ;
    __half* hK = (__half*)pK;
    __half* hV = (__half*)pV;
    float* fT = (float*)pTmp; float* fX = (float*)pX1;
    __half* actA = (__half*)pA;       // query act -> ctx -> LN1 act
    __half* actB = (__half*)pB;       // key act | value act -> FFN1 out
    __half* actK = actB;
    __half* actV = actB + (size_t)MM * EE;
    __half* ws   = (__half*)pW;

    const int ATTN_SMEM = (128 * AST + 4 * 64 * AST) * 2;  // 55296 bytes
    cudaFuncSetAttribute(attn_mma,
                         cudaFuncAttributeMaxDynamicSharedMemorySize, ATTN_SMEM);

    dim3 gE(EE / 128, MM / 128);          // (4, 64)
    dim3 gF(FF / 128, MM / 128);          // (16, 64)
    dim3 gP(EE / 128, MM / 128, 3);       // 3-in-1 projection
    dim3 wblk(32, 8);
    int actBlocks = 3 * (MM * EE / 512);  // 24576

    // 0: all act conversions ; 1: all weight conversions
    prep_act<<<actBlocks, 256>>>(query, key_t, value, actA, actK, actV);
    prep_wt<<<3072, wblk>>>(Wq, Wk, Wv, Wo, W1, W2, ws);

    // 2: QKV projections (one launch, z-selected)
    Proj3 p3;
    p3.A[0] = actA;          p3.A[1] = actK;          p3.A[2] = actV;
    p3.Bw[0] = ws + WOFF_Q;  p3.Bw[1] = ws + WOFF_K;  p3.Bw[2] = ws + WOFF_V;
    p3.bias[0] = bq;         p3.bias[1] = bk;         p3.bias[2] = bv;
    p3.out[0] = hQ;          p3.out[1] = hK;          p3.out[2] = hV;
    mma_gemm_proj<<<gP, 256>>>(p3);

    // 3: HMMA flash attention -> fp16 ctx in actA
    attn_mma<<<dim3(SS / 128, HH, BB), 256, ATTN_SMEM>>>(hQ, hK, hV, actA);

    // 4: O projection + residual(query)
    mma_gemm<1><<<gE, 256>>>(actA, ws + WOFF_O, bo, query, fT, nullptr, EE, EE);
    // 5: LN1 -> x1 fp32 + fp16 in actA
    ln_kernel<<<MM, 256>>>(fT, g1, be1, fX, actA);
    // 6: FFN1 + exact GELU -> fp16 in actB
    mma_gemm<2><<<gF, 256>>>(actA, ws + WOFF_1, b1, nullptr, nullptr, actB, FF, EE);
    // 7: FFN2 + residual(x1)
    mma_gemm<1><<<gE, 256>>>(actB, ws + WOFF_2, b2, fX, fT, nullptr, EE, FF);
    // 8: LN2 -> out
    ln_kernel<<<MM, 256>>>(fT, g2, be2, out, nullptr);
}

// round 17
// speedup vs baseline: 2.2398x; 1.0223x over previous
#include <cuda_runtime.h>
#include <cuda_fp16.h>
#include <math.h>
#include <stdint.h>

// Problem dims (fixed)
#define BB 4
#define SS 2048
#define EE 512
#define HH 8
#define DD 64
#define FF 2048
#define MM (BB*SS)          // 8192 tokens
#define LN_EPS 1e-5f

// weight offsets in g_ws (fp16 elems)
#define WOFF_Q  0u
#define WOFF_K  262144u
#define WOFF_V  524288u
#define WOFF_O  786432u
#define WOFF_1  1048576u
#define WOFF_2  2097152u

// ---------------- scratch (device globals; no allocation) ----------------
__device__ __half g_Qh[(size_t)MM*EE];
__device__ __half g_Kh[(size_t)MM*EE];
__device__ __half g_Vh[(size_t)MM*EE];
__device__ float g_tmp[MM*EE];
__device__ float g_x1 [MM*EE];
__device__ __half g_actA[(size_t)MM*EE];    // query act -> ctx -> LN1 act
__device__ __half g_actB[(size_t)MM*FF];    // key act | value act -> FFN1 output
__device__ __half g_ws  [(size_t)4*1024*1024]; // all 6 converted weights

// ================= helpers =================
__device__ __forceinline__ uint32_t smem_u32(const void* p) {
    uint32_t a;
    asm("{ .reg .u64 t; cvta.to.shared.u64 t, %1; cvt.u32.u64 %0, t; }"
        : "=r"(a) : "l"(p));
    return a;
}
__device__ __forceinline__ void cpasync16(uint32_t s, const void* g) {
    asm volatile("cp.async.cg.shared.global [%0], [%1], 16;" :: "r"(s), "l"(g));
}
__device__ __forceinline__ void cp_commit() {
    asm volatile("cp.async.commit_group;" ::: "memory");
}
__device__ __forceinline__ void ldm_x4(uint32_t* r, uint32_t addr) {
    asm volatile("ldmatrix.sync.aligned.m8n8.x4.shared.b16 {%0,%1,%2,%3}, [%4];"
        : "=r"(r[0]), "=r"(r[1]), "=r"(r[2]), "=r"(r[3]) : "r"(addr));
}
__device__ __forceinline__ void ldm_x4_t(uint32_t* r, uint32_t addr) {
    asm volatile("ldmatrix.sync.aligned.m8n8.x4.trans.shared.b16 {%0,%1,%2,%3}, [%4];"
        : "=r"(r[0]), "=r"(r[1]), "=r"(r[2]), "=r"(r[3]) : "r"(addr));
}
__device__ __forceinline__ void mma_f16(float* c, const uint32_t* a,
                                        uint32_t b0, uint32_t b1) {
    asm volatile(
        "mma.sync.aligned.m16n8k16.row.col.f32.f16.f16.f32 "
        "{%0,%1,%2,%3}, {%4,%5,%6,%7}, {%8,%9}, {%0,%1,%2,%3};"
        : "+f"(c[0]), "+f"(c[1]), "+f"(c[2]), "+f"(c[3])
        : "r"(a[0]), "r"(a[1]), "r"(a[2]), "r"(a[3]), "r"(b0), "r"(b1));
}
__device__ __forceinline__ uint32_t pk2hf(float a, float b) {
    __half2 t = __floats2half2_rn(a, b);
    return *reinterpret_cast<uint32_t*>(&t);
}
__device__ __forceinline__ float ex2f(float x) {
    float r;
    asm("ex2.approx.f32 %0, %1;" : "=f"(r) : "f"(x));
    return r;
}
__device__ __forceinline__ uint32_t ex2h2(uint32_t x) {
    uint32_t r;
    asm("ex2.approx.f16x2 %0, %1;" : "=r"(r) : "r"(x));
    return r;
}

// ================= GEMM core (shared by both GEMM kernels) =================
// Tile 128x128, BK=32, 8 warps (4m x 2n), 2-stage double buffer.
#define SROW 40

#define GEMM_CORE(Aptr, Bptr, K2)                                               \
    __shared__ __half As[2][128 * SROW];                                        \
    __shared__ __half Bs[2][128 * SROW];                                        \
    const int tid = threadIdx.x;                                                \
    const int wid = tid >> 5, lid = tid & 31;                                   \
    const int warp_m = wid & 3;                                                 \
    const int warp_n = wid >> 2;                                                \
    const int m0 = blockIdx.y * 128;                                            \
    const int n0 = blockIdx.x * 128;                                            \
    const uint32_t sA0 = smem_u32(As[0]), sA1 = smem_u32(As[1]);                \
    const uint32_t sB0 = smem_u32(Bs[0]), sB1 = smem_u32(Bs[1]);                \
    float acc[2][8][4];                                                         \
    _Pragma("unroll")                                                           \
    for (int mt = 0; mt < 2; mt++)                                              \
        _Pragma("unroll")                                                       \
        for (int nt = 0; nt < 8; nt++)                                          \
            _Pragma("unroll")                                                   \
            for (int q = 0; q < 4; q++) acc[mt][nt][q] = 0.f;                   \
    const int nK = (K2) / 32;                                                   \
    const int r0c = tid >> 2, c0c = (tid & 3);                                  \
    const int r1c = (tid + 256) >> 2, c1c = ((tid + 256) & 3);                  \
    const uint32_t so0 = (uint32_t)(r0c * SROW + c0c * 8) * 2;                  \
    const uint32_t so1 = (uint32_t)(r1c * SROW + c1c * 8) * 2;                  \
    ISSUE(Aptr, Bptr, K2, 0, 0);                                                \
    for (int kt = 0; kt < nK; kt++) {                                           \
        const int b = kt & 1;                                                   \
        if (kt + 1 < nK) {                                                      \
            ISSUE(Aptr, Bptr, K2, kt + 1, b ^ 1);                               \
            asm volatile("cp.async.wait_group 1;" ::: "memory");                \
        } else {                                                                \
            asm volatile("cp.async.wait_group 0;" ::: "memory");                \
        }                                                                       \
        __syncthreads();                                                        \
        const uint32_t sAb = b ? sA1 : sA0;                                     \
        const uint32_t sBb = b ? sB1 : sB0;                                     \
        _Pragma("unroll")                                                       \
        for (int ks = 0; ks < 2; ks++) {                                        \
            const int kof = ks * 16;                                            \
            uint32_t afr[2][4];                                                 \
            _Pragma("unroll")                                                   \
            for (int mt = 0; mt < 2; mt++) {                                    \
                uint32_t addr = sAb +                                           \
                    (uint32_t)((warp_m * 32 + mt * 16 + (lid & 15)) * SROW      \
                               + kof + (lid >> 4) * 8) * 2;                     \
                ldm_x4(afr[mt], addr);                                          \
            }                                                                   \
            uint32_t bfr[4][4];                                                 \
            _Pragma("unroll")                                                   \
            for (int q = 0; q < 4; q++) {                                       \
                const int grp = lid >> 3;                                       \
                const int n = warp_n * 64 + q * 16 + (grp >> 1) * 8 + (lid & 7);\
                uint32_t addr = sBb +                                           \
                    (uint32_t)(n * SROW + kof + (grp & 1) * 8) * 2;             \
                ldm_x4(bfr[q], addr);                                           \
            }                                                                   \
            _Pragma("unroll")                                                   \
            for (int mt = 0; mt < 2; mt++)                                      \
                _Pragma("unroll")                                               \
                for (int nt = 0; nt < 8; nt++)                                  \
                    mma_f16(acc[mt][nt], afr[mt],                               \
                            bfr[nt >> 1][(nt & 1) * 2],                         \
                            bfr[nt >> 1][(nt & 1) * 2 + 1]);                    \
        }                                                                       \
        __syncthreads();                                                        \
    }

#define ISSUE(Aptr, Bptr, K2, kt, b) do {                                       \
        const __half* Ag = (Aptr) + (size_t)m0 * (K2) + (size_t)(kt) * 32;      \
        const __half* Bg = (Bptr) + (size_t)n0 * (K2) + (size_t)(kt) * 32;      \
        uint32_t _a = (b) ? sA1 : sA0, _b = (b) ? sB1 : sB0;                    \
        cpasync16(_a + so0, Ag + (size_t)r0c * (K2) + c0c * 8);                 \
        cpasync16(_a + so1, Ag + (size_t)r1c * (K2) + c1c * 8);                 \
        cpasync16(_b + so0, Bg + (size_t)r0c * (K2) + c0c * 8);                 \
        cpasync16(_b + so1, Bg + (size_t)r1c * (K2) + c1c * 8);                 \
        cp_commit();                                                            \
    } while (0)

// ---- general GEMM: EPI 1 = +bias+res fp32 ; 2 = gelu(+bias) -> fp16 ----
template<int EPI>
__global__ __launch_bounds__(256) void mma_gemm(
    const __half* __restrict__ A, const __half* __restrict__ Bw,
    const float* __restrict__ bias, const float* __restrict__ res,
    float* __restrict__ C, __half* __restrict__ Cs,
    int N, int K2)
{
    GEMM_CORE(A, Bw, K2)

    const int g = lid >> 2, tig = lid & 3;
    const int row_base = m0 + warp_m * 32;
    const int col_base = n0 + warp_n * 64;
    #pragma unroll
    for (int mt = 0; mt < 2; mt++) {
        #pragma unroll
        for (int half = 0; half < 2; half++) {
            const int r = row_base + mt * 16 + g + half * 8;
            #pragma unroll
            for (int nt = 0; nt < 8; nt++) {
                const int cidx = col_base + nt * 8 + tig * 2;
                float v0 = acc[mt][nt][half * 2 + 0] + bias[cidx];
                float v1 = acc[mt][nt][half * 2 + 1] + bias[cidx + 1];
                if (EPI == 1) {
                    const float2 rv = *(const float2*)(res + (size_t)r * N + cidx);
                    v0 += rv.x; v1 += rv.y;
                    *(float2*)(C + (size_t)r * N + cidx) = make_float2(v0, v1);
                }
                if (EPI == 2) {
                    v0 = 0.5f * v0 * (1.0f + erff(v0 * 0.70710678118654752f));
                    v1 = 0.5f * v1 * (1.0f + erff(v1 * 0.70710678118654752f));
                    *(uint32_t*)(Cs + (size_t)r * N + cidx) = pk2hf(v0, v1);
                }
            }
        }
    }
}

// ---- 3-in-1 projection GEMM: z selects (A, W, bias, out, scale); +bias -> fp16 ----
struct Proj3 {
    const __half* A[3];
    const __half* Bw[3];
    const float*  bias[3];
    __half*       out[3];
    float         scale[3];
};

__global__ __launch_bounds__(256) void mma_gemm_proj(Proj3 p)
{
    const __half* Ap  = p.A[blockIdx.z];
    const __half* Bwp = p.Bw[blockIdx.z];
    const float*  bp  = p.bias[blockIdx.z];
    __half*       op  = p.out[blockIdx.z];
    const float   sc  = p.scale[blockIdx.z];

    GEMM_CORE(Ap, Bwp, EE)

    const int g = lid >> 2, tig = lid & 3;
    const int row_base = m0 + warp_m * 32;
    const int col_base = n0 + warp_n * 64;
    #pragma unroll
    for (int mt = 0; mt < 2; mt++) {
        #pragma unroll
        for (int half = 0; half < 2; half++) {
            const int r = row_base + mt * 16 + g + half * 8;
            #pragma unroll
            for (int nt = 0; nt < 8; nt++) {
                const int cidx = col_base + nt * 8 + tig * 2;
                float v0 = (acc[mt][nt][half * 2 + 0] + bp[cidx])     * sc;
                float v1 = (acc[mt][nt][half * 2 + 1] + bp[cidx + 1]) * sc;
                *(uint32_t*)(op + (size_t)r * EE + cidx) = pk2hf(v0, v1);
            }
        }
    }
}

// ================= HMMA flash attention (fp16, log2-domain softmax) =================
// Q pre-scaled by (1/8)*log2(e) -> scores are log2-domain; P = 2^(s-m).
#define AST 72   // smem row stride (fp16) = 144B -> ldmatrix conflict-free

__global__ __launch_bounds__(256, 2) void attn_mma(
    const __half* __restrict__ Q, const __half* __restrict__ K,
    const __half* __restrict__ V, __half* __restrict__ Os)
{
    extern __shared__ __half smem[];
    const uint32_t sQ = smem_u32(smem);
    const uint32_t sK0 = sQ + 128 * AST * 2;
    const uint32_t sV0 = sK0 + 64 * AST * 2;
    const uint32_t sK1 = sV0 + 64 * AST * 2;
    const uint32_t sV1 = sK1 + 64 * AST * 2;

    const int tid = threadIdx.x;
    const int wid = tid >> 5, lid = tid & 31;
    const int g = lid >> 2, tig = lid & 3;
    const int h = blockIdx.y, b = blockIdx.z;
    const int q0 = blockIdx.x * 128;

    const __half* Qg = Q + ((size_t)(b * SS + q0)) * EE + h * DD;
    const __half* Kg = K + ((size_t)(b * SS)) * EE + h * DD;
    const __half* Vg = V + ((size_t)(b * SS)) * EE + h * DD;

    #pragma unroll
    for (int i = 0; i < 4; i++) {
        int idx = tid + i * 256;
        int row = idx >> 3, c8 = (idx & 7) * 8;
        cpasync16(sQ + (uint32_t)(row * AST + c8) * 2, Qg + (size_t)row * EE + c8);
    }

    #define KV_ISSUE(kt, kbuf, vbuf) do {                                   \
        int base_ = (kt) * 64;                                              \
        _Pragma("unroll")                                                   \
        for (int i_ = 0; i_ < 2; i_++) {                                    \
            int idx_ = tid + i_ * 256;                                      \
            int row_ = idx_ >> 3, c8_ = (idx_ & 7) * 8;                     \
            cpasync16((kbuf) + (uint32_t)(row_ * AST + c8_) * 2,            \
                      Kg + (size_t)(base_ + row_) * EE + c8_);              \
            cpasync16((vbuf) + (uint32_t)(row_ * AST + c8_) * 2,            \
                      Vg + (size_t)(base_ + row_) * EE + c8_);              \
        }                                                                   \
        cp_commit();                                                        \
    } while (0)

    KV_ISSUE(0, sK0, sV0);

    float m_run[2] = {-1e30f, -1e30f}, l_run[2] = {0.f, 0.f};
    float oacc[8][4];
    #pragma unroll
    for (int nt = 0; nt < 8; nt++)
        #pragma unroll
        for (int q = 0; q < 4; q++) oacc[nt][q] = 0.f;

    uint32_t qfr[4][4];

    for (int kt = 0; kt < SS / 64; kt++) {
        const int buf = kt & 1;
        const uint32_t kb = buf ? sK1 : sK0;
        const uint32_t vb = buf ? sV1 : sV0;
        if (kt + 1 < SS / 64) {
            const uint32_t nk = buf ? sK0 : sK1;
            const uint32_t nv = buf ? sV0 : sV1;
            KV_ISSUE(kt + 1, nk, nv);
            asm volatile("cp.async.wait_group 1;" ::: "memory");
        } else {
            asm volatile("cp.async.wait_group 0;" ::: "memory");
        }
        __syncthreads();

        if (kt == 0) {
            #pragma unroll
            for (int ks = 0; ks < 4; ks++) {
                uint32_t addr = sQ +
                    (uint32_t)((wid * 16 + (lid & 15)) * AST + ks * 16 + (lid >> 4) * 8) * 2;
                ldm_x4(qfr[ks], addr);
            }
        }

        // ---- S = Q' @ K^T (log2 domain) ----
        float sfr[8][4];
        #pragma unroll
        for (int nt = 0; nt < 8; nt++)
            #pragma unroll
            for (int q = 0; q < 4; q++) sfr[nt][q] = 0.f;

        const int grp = lid >> 3;
        #pragma unroll
        for (int ks = 0; ks < 4; ks++) {
            uint32_t bfr[4][4];
            #pragma unroll
            for (int q = 0; q < 4; q++) {
                const int n = q * 16 + (grp >> 1) * 8 + (lid & 7);
                uint32_t addr = kb + (uint32_t)(n * AST + ks * 16 + (grp & 1) * 8) * 2;
                ldm_x4(bfr[q], addr);
            }
            #pragma unroll
            for (int nt = 0; nt < 8; nt++)
                mma_f16(sfr[nt], qfr[ks],
                        bfr[nt >> 1][(nt & 1) * 2],
                        bfr[nt >> 1][(nt & 1) * 2 + 1]);
        }

        // ---- online softmax (log2 domain, h2 exp); P stored into sfr[.][half*2] ----
        #pragma unroll
        for (int half = 0; half < 2; half++) {
            float mloc = -1e30f;
            #pragma unroll
            for (int nt = 0; nt < 8; nt++)
                mloc = fmaxf(mloc, fmaxf(sfr[nt][half*2], sfr[nt][half*2+1]));
            mloc = fmaxf(mloc, __shfl_xor_sync(0xffffffffu, mloc, 1));
            mloc = fmaxf(mloc, __shfl_xor_sync(0xffffffffu, mloc, 2));
            float m_new = fmaxf(m_run[half], mloc);
            float corr = ex2f(m_run[half] - m_new);
            m_run[half] = m_new;
            float lsum = 0.f;
            #pragma unroll
            for (int nt = 0; nt < 8; nt++) {
                uint32_t p2 = ex2h2(pk2hf(sfr[nt][half*2]   - m_new,
                                          sfr[nt][half*2+1] - m_new));
                sfr[nt][half*2] = __uint_as_float(p2);   // P fragment pair
                float2 pf = __half22float2(*(__half2*)&p2);
                lsum += pf.x + pf.y;
            }
            lsum += __shfl_xor_sync(0xffffffffu, lsum, 1);
            lsum += __shfl_xor_sync(0xffffffffu, lsum, 2);
            l_run[half] = l_run[half] * corr + lsum;
            #pragma unroll
            for (int nt = 0; nt < 8; nt++) {
                oacc[nt][half*2]   *= corr;
                oacc[nt][half*2+1] *= corr;
            }
        }

        // ---- O += P @ V ----
        #pragma unroll
        for (int j = 0; j < 4; j++) {
            uint32_t pfr[4];
            pfr[0] = __float_as_uint(sfr[2*j][0]);
            pfr[1] = __float_as_uint(sfr[2*j][2]);
            pfr[2] = __float_as_uint(sfr[2*j+1][0]);
            pfr[3] = __float_as_uint(sfr[2*j+1][2]);
            #pragma unroll
            for (int dp = 0; dp < 4; dp++) {
                uint32_t vfr[4];
                uint32_t addr = vb +
                    (uint32_t)((j * 16 + (lid & 15)) * AST + dp * 16 + (lid >> 4) * 8) * 2;
                ldm_x4_t(vfr, addr);
                mma_f16(oacc[dp*2],     pfr, vfr[0], vfr[1]);
                mma_f16(oacc[dp*2 + 1], pfr, vfr[2], vfr[3]);
            }
        }
        __syncthreads();
    }
    #undef KV_ISSUE

    // ---- epilogue: plain fp16 ctx [M, EE] ----
    const size_t rowBase = (size_t)(b * SS + q0);
    #pragma unroll
    for (int half = 0; half < 2; half++) {
        float inv = 1.0f / l_run[half];
        size_t m = rowBase + wid * 16 + g + half * 8;
        size_t base = m * EE + h * DD + tig * 2;
        #pragma unroll
        for (int nt = 0; nt < 8; nt++) {
            float o0 = oacc[nt][half*2]     * inv;
            float o1 = oacc[nt][half*2 + 1] * inv;
            *(uint32_t*)(Os + base + nt * 8) = pk2hf(o0, o1);
        }
    }
}

// ================= fused prep kernels =================
__global__ __launch_bounds__(256) void prep_act(
    const float* __restrict__ q, const float* __restrict__ k,
    const float* __restrict__ v,
    __half* __restrict__ aq, __half* __restrict__ ak, __half* __restrict__ av)
{
    const size_t per = (size_t)MM * EE / 2;
    size_t idx = (size_t)blockIdx.x * 256 + threadIdx.x;
    const float* src; __half* dst; size_t o;
    if (idx < per)            { src = q; dst = aq; o = idx; }
    else if (idx < 2 * per)   { src = k; dst = ak; o = idx - per; }
    else                      { src = v; dst = av; o = idx - 2 * per; }
    float2 x = ((const float2*)src)[o];
    ((uint32_t*)dst)[o] = pk2hf(x.x, x.y);
}

__global__ void prep_wt(
    const float* __restrict__ Wq, const float* __restrict__ Wk,
    const float* __restrict__ Wv, const float* __restrict__ Wo,
    const float* __restrict__ W1, const float* __restrict__ W2,
    __half* __restrict__ ws)
{
    __shared__ float t[32][33];
    const int tI = blockIdx.x;
    const float* W; __half* Ws; int K, N, n0, k0;
    if (tI < 1024) {
        int w = tI >> 8, tt = tI & 255;
        W  = (w == 0) ? Wq : (w == 1) ? Wk : (w == 2) ? Wv : Wo;
        Ws = ws + (size_t)w * 262144u;
        K = 512; N = 512;
        n0 = (tt & 15) * 32; k0 = (tt >> 4) * 32;
    } else if (tI < 2048) {
        int tt = tI - 1024;
        W = W1; Ws = ws + WOFF_1;
        K = 512; N = 2048;
        n0 = (tt & 63) * 32; k0 = (tt >> 6) * 32;
    } else {
        int tt = tI - 2048;
        W = W2; Ws = ws + WOFF_2;
        K = 2048; N = 512;
        n0 = (tt & 15) * 32; k0 = (tt >> 4) * 32;
    }
    for (int i = threadIdx.y; i < 32; i += 8)
        t[i][threadIdx.x] = W[(size_t)(k0 + i) * N + n0 + threadIdx.x];
    __syncthreads();
    for (int i = threadIdx.y; i < 32; i += 8) {
        int n = n0 + i, k = k0 + threadIdx.x;
        Ws[(size_t)n * K + k] = __float2half_rn(t[threadIdx.x][i]);
    }
}

// ---------------- layernorm (optional fp16 out) ----------------
__global__ __launch_bounds__(256) void ln_kernel(
    const float* __restrict__ x, const float* __restrict__ g,
    const float* __restrict__ be, float* __restrict__ y,
    __half* __restrict__ ys)
{
    __shared__ float red[16];
    const int row = blockIdx.x;
    const int tid = threadIdx.x;
    const float* xr = x + (size_t)row * EE;

    float v0 = xr[tid], v1 = xr[tid + 256];
    float s  = v0 + v1;
    float ss = v0*v0 + v1*v1;
    #pragma unroll
    for (int off = 16; off > 0; off >>= 1) {
        s  += __shfl_xor_sync(0xffffffffu, s,  off);
        ss += __shfl_xor_sync(0xffffffffu, ss, off);
    }
    int wid = tid >> 5, lid = tid & 31;
    if (lid == 0) { red[wid] = s; red[wid + 8] = ss; }
    __syncthreads();
    if (tid < 32) {
        float a = (tid < 8)  ? red[tid]     : 0.f;
        float c = (tid < 8)  ? red[tid + 8] : 0.f;
        #pragma unroll
        for (int off = 4; off > 0; off >>= 1) {
            a += __shfl_xor_sync(0xffffffffu, a, off);
            c += __shfl_xor_sync(0xffffffffu, c, off);
        }
        if (tid == 0) { red[0] = a; red[1] = c; }
    }
    __syncthreads();
    float mean = red[0] * (1.0f / EE);
    float var  = fmaxf(red[1] * (1.0f / EE) - mean * mean, 0.f);
    float rstd = rsqrtf(var + LN_EPS);

    float o0 = (v0 - mean) * rstd * g[tid]       + be[tid];
    float o1 = (v1 - mean) * rstd * g[tid + 256] + be[tid + 256];
    float* yr = y + (size_t)row * EE;
    yr[tid] = o0; yr[tid + 256] = o1;

    if (ys) {
        size_t base = (size_t)row * EE;
        ys[base + tid]       = __float2half_rn(o0);
        ys[base + tid + 256] = __float2half_rn(o1);
    }
}

// ---------------- launch ----------------
extern "C" void kernel_launch(void* const* d_in, const int* in_sizes, int n_in,
                              void* d_out, int out_size)
{
    (void)in_sizes; (void)n_in; (void)out_size;
    const float* query = (const float*)d_in[0];
    const float* key_t = (const float*)d_in[1];
    const float* value = (const float*)d_in[2];
    const float* Wq = (const float*)d_in[3];  const float* bq = (const float*)d_in[4];
    const float* Wk = (const float*)d_in[5];  const float* bk = (const float*)d_in[6];
    const float* Wv = (const float*)d_in[7];  const float* bv = (const float*)d_in[8];
    const float* Wo = (const float*)d_in[9];  const float* bo = (const float*)d_in[10];
    const float* g1 = (const float*)d_in[11]; const float* be1 = (const float*)d_in[12];
    const float* g2 = (const float*)d_in[13]; const float* be2 = (const float*)d_in[14];
    const float* W1 = (const float*)d_in[15]; const float* b1 = (const float*)d_in[16];
    const float* W2 = (const float*)d_in[17]; const float* b2 = (const float*)d_in[18];
    float* out = (float*)d_out;

    void *pQ, *pK, *pV, *pTmp, *pX1, *pA, *pB, *pW;
    cudaGetSymbolAddress(&pQ,   g_Qh);
    cudaGetSymbolAddress(&pK,   g_Kh);
    cudaGetSymbolAddress(&pV,   g_Vh);
    cudaGetSymbolAddress(&pTmp, g_tmp);
    cudaGetSymbolAddress(&pX1,  g_x1);
    cudaGetSymbolAddress(&pA,   g_actA);
    cudaGetSymbolAddress(&pB,   g_actB);
    cudaGetSymbolAddress(&pW,   g_ws);
    __half* hQ = (__half*)pQ;
    __half* hK = (__half*)pK;
    __half* hV = (__half*)pV;
    float* fT = (float*)pTmp; float* fX = (float*)pX1;
    __half* actA = (__half*)pA;
    __half* actB = (__half*)pB;
    __half* actK = actB;
    __half* actV = actB + (size_t)MM * EE;
    __half* ws   = (__half*)pW;

    const int ATTN_SMEM = (128 * AST + 4 * 64 * AST) * 2;  // 55296 bytes
    cudaFuncSetAttribute(attn_mma,
                         cudaFuncAttributeMaxDynamicSharedMemorySize, ATTN_SMEM);

    dim3 gE(EE / 128, MM / 128);
    dim3 gF(FF / 128, MM / 128);
    dim3 gP(EE / 128, MM / 128, 3);
    dim3 wblk(32, 8);
    int actBlocks = 3 * (MM * EE / 512);

    // 0: all act conversions ; 1: all weight conversions
    prep_act<<<actBlocks, 256>>>(query, key_t, value, actA, actK, actV);
    prep_wt<<<3072, wblk>>>(Wq, Wk, Wv, Wo, W1, W2, ws);

    // 2: QKV projections (one launch, z-selected; Q pre-scaled into log2 domain)
    Proj3 p3;
    p3.A[0] = actA;          p3.A[1] = actK;          p3.A[2] = actV;
    p3.Bw[0] = ws + WOFF_Q;  p3.Bw[1] = ws + WOFF_K;  p3.Bw[2] = ws + WOFF_V;
    p3.bias[0] = bq;         p3.bias[1] = bk;         p3.bias[2] = bv;
    p3.out[0] = hQ;          p3.out[1] = hK;          p3.out[2] = hV;
    p3.scale[0] = 0.125f * 1.44269504088896340736f;
    p3.scale[1] = 1.0f;      p3.scale[2] = 1.0f;
    mma_gemm_proj<<<gP, 256>>>(p3);

    // 3: HMMA flash attention -> fp16 ctx in actA
    attn_mma<<<dim3(SS / 128, HH, BB), 256, ATTN_SMEM>>>(hQ, hK, hV, actA);

    // 4: O projection + residual(query)
    mma_gemm<1><<<gE, 256>>>(actA, ws + WOFF_O, bo, query, fT, nullptr, EE, EE);
    // 5: LN1 -> x1 fp32 + fp16 in actA
    ln_kernel<<<MM, 256>>>(fT, g1, be1, fX, actA);
    // 6: FFN1 + exact GELU -> fp16 in actB
    mma_gemm<2><<<gF, 256>>>(actA, ws + WOFF_1, b1, nullptr, nullptr, actB, FF, EE);
    // 7: FFN2 + residual(x1)
    mma_gemm<1><<<gE, 256>>>(actB, ws + WOFF_2, b2, fX, fT, nullptr, EE, FF);
    // 8: LN2 -> out
    ln_kernel<<<MM, 256>>>(fT, g2, be2, out, nullptr);
}